// round 1
// baseline (speedup 1.0000x reference)
#include <cuda_runtime.h>
#include <cstdint>

#define NROWS 100000
#define DCOLS 256
#define NEDGE 3200000

// ---------------- scratch (device globals: allocation-free) ----------------
__device__ float g_bufA[(size_t)NROWS * DCOLS];   // ping
__device__ float g_bufB[(size_t)NROWS * DCOLS];   // pong
__device__ int   g_counts[NROWS];
__device__ int   g_row_start[NROWS + 1];
__device__ int   g_cursor[NROWS];
__device__ int   g_csr_col[NEDGE];
__device__ float g_csr_w[NEDGE];

// ---------------- GEMM: support = x @ weight; out = support + bias ---------
#define BM 64
#define BN 64
#define BK 16

__global__ void gemm_kernel(const float* __restrict__ x,
                            const float* __restrict__ w,
                            const float* __restrict__ bias,
                            float* __restrict__ out, int M)
{
    __shared__ float As[BK][BM];
    __shared__ float Bs[BK][BN];

    const int tid = threadIdx.x;          // 256 threads
    const int tx = tid & 15;              // 0..15
    const int ty = tid >> 4;              // 0..15
    const int row0 = blockIdx.y * BM;
    const int col0 = blockIdx.x * BN;

    // A-load mapping: 64 rows x 16 k, float4 along k
    const int ar = tid >> 2;              // 0..63
    const int ak = (tid & 3) * 4;         // 0,4,8,12
    // B-load mapping: 16 rows x 64 cols, float4 along cols
    const int br = tid >> 4;              // 0..15
    const int bc = (tid & 15) * 4;        // 0..60

    float acc[4][4];
#pragma unroll
    for (int i = 0; i < 4; i++)
#pragma unroll
        for (int j = 0; j < 4; j++) acc[i][j] = 0.0f;

    for (int k0 = 0; k0 < DCOLS; k0 += BK) {
        float4 av = make_float4(0.f, 0.f, 0.f, 0.f);
        const int arow = row0 + ar;
        if (arow < M)
            av = *(const float4*)(x + (size_t)arow * DCOLS + k0 + ak);
        As[ak + 0][ar] = av.x;
        As[ak + 1][ar] = av.y;
        As[ak + 2][ar] = av.z;
        As[ak + 3][ar] = av.w;

        float4 bv = *(const float4*)(w + (size_t)(k0 + br) * DCOLS + col0 + bc);
        *(float4*)(&Bs[br][bc]) = bv;
        __syncthreads();

#pragma unroll
        for (int k = 0; k < BK; k++) {
            float4 a4 = *(const float4*)(&As[k][ty * 4]);
            float4 b4 = *(const float4*)(&Bs[k][tx * 4]);
            float a[4] = {a4.x, a4.y, a4.z, a4.w};
            float b[4] = {b4.x, b4.y, b4.z, b4.w};
#pragma unroll
            for (int i = 0; i < 4; i++)
#pragma unroll
                for (int j = 0; j < 4; j++)
                    acc[i][j] = fmaf(a[i], b[j], acc[i][j]);
        }
        __syncthreads();
    }

    float4 bb = *(const float4*)(bias + col0 + tx * 4);
#pragma unroll
    for (int i = 0; i < 4; i++) {
        const int r = row0 + ty * 4 + i;
        if (r < M) {
            const size_t o = (size_t)r * DCOLS + col0 + tx * 4;
            float4 s = make_float4(acc[i][0], acc[i][1], acc[i][2], acc[i][3]);
            *(float4*)(g_bufA + o) = s;
            float4 ob = make_float4(s.x + bb.x, s.y + bb.y, s.z + bb.z, s.w + bb.w);
            *(float4*)(out + o) = ob;
        }
    }
}

// ---------------- CSR build ----------------
__global__ void zero_counts_kernel(int M)
{
    for (int i = blockIdx.x * blockDim.x + threadIdx.x; i < M;
         i += gridDim.x * blockDim.x)
        g_counts[i] = 0;
}

__global__ void count_kernel(const int* __restrict__ erow, int E)
{
    for (int i = blockIdx.x * blockDim.x + threadIdx.x; i < E;
         i += gridDim.x * blockDim.x)
        atomicAdd(&g_counts[erow[i]], 1);
}

__global__ void scan_kernel(int M)
{
    __shared__ int sh[1024];
    const int t = threadIdx.x;
    const int CH = (M + 1023) / 1024;
    int begin = t * CH;
    int end = begin + CH;
    if (begin > M) begin = M;
    if (end > M) end = M;

    int sum = 0;
    for (int i = begin; i < end; i++) sum += g_counts[i];
    sh[t] = sum;
    __syncthreads();

    // inclusive scan (Hillis-Steele)
    for (int d = 1; d < 1024; d <<= 1) {
        int v = (t >= d) ? sh[t - d] : 0;
        __syncthreads();
        sh[t] += v;
        __syncthreads();
    }

    int run = (t == 0) ? 0 : sh[t - 1];
    for (int i = begin; i < end; i++) {
        g_row_start[i] = run;
        g_cursor[i] = run;
        run += g_counts[i];
    }
    if (t == 1023) g_row_start[M] = sh[1023];
}

__global__ void scatter_kernel(const int* __restrict__ erow,
                               const int* __restrict__ ecol,
                               const float* __restrict__ ew, int E)
{
    for (int i = blockIdx.x * blockDim.x + threadIdx.x; i < E;
         i += gridDim.x * blockDim.x) {
        const int r = erow[i];
        const int pos = atomicAdd(&g_cursor[r], 1);
        g_csr_col[pos] = ecol[i];
        g_csr_w[pos] = ew[i];
    }
}

// ---------------- SpMM (gather form): nxt[r] = sum w_e * cur[col_e]; out += nxt
__device__ __forceinline__ void fma4(float4& a, float w, const float4& v)
{
    a.x = fmaf(w, v.x, a.x);
    a.y = fmaf(w, v.y, a.y);
    a.z = fmaf(w, v.z, a.z);
    a.w = fmaf(w, v.w, a.w);
}

__global__ void spmm_kernel(int flip, float* __restrict__ out, int M)
{
    const float* __restrict__ cur = flip ? g_bufB : g_bufA;
    float* __restrict__ nxt = flip ? g_bufA : g_bufB;

    const int warp = (blockIdx.x * blockDim.x + threadIdx.x) >> 5;
    if (warp >= M) return;
    const int lane = threadIdx.x & 31;
    const int off = lane * 8;             // 8 floats per lane

    const int s = g_row_start[warp];
    const int e = g_row_start[warp + 1];

    float4 acc0 = make_float4(0.f, 0.f, 0.f, 0.f);
    float4 acc1 = make_float4(0.f, 0.f, 0.f, 0.f);

    int j = s;
    for (; j + 1 < e; j += 2) {
        const int c0 = g_csr_col[j];
        const int c1 = g_csr_col[j + 1];
        const float w0 = g_csr_w[j];
        const float w1 = g_csr_w[j + 1];
        const float4* p0 = (const float4*)(cur + (size_t)c0 * DCOLS + off);
        const float4* p1 = (const float4*)(cur + (size_t)c1 * DCOLS + off);
        float4 u0 = p0[0], u1 = p0[1];
        float4 v0 = p1[0], v1 = p1[1];
        fma4(acc0, w0, u0);
        fma4(acc1, w0, u1);
        fma4(acc0, w1, v0);
        fma4(acc1, w1, v1);
    }
    if (j < e) {
        const int c0 = g_csr_col[j];
        const float w0 = g_csr_w[j];
        const float4* p0 = (const float4*)(cur + (size_t)c0 * DCOLS + off);
        float4 u0 = p0[0], u1 = p0[1];
        fma4(acc0, w0, u0);
        fma4(acc1, w0, u1);
    }

    const size_t o = (size_t)warp * DCOLS + off;
    *(float4*)(nxt + o) = acc0;
    *(float4*)(nxt + o + 4) = acc1;

    float4 d0 = *(const float4*)(out + o);
    float4 d1 = *(const float4*)(out + o + 4);
    d0.x += acc0.x; d0.y += acc0.y; d0.z += acc0.z; d0.w += acc0.w;
    d1.x += acc1.x; d1.y += acc1.y; d1.z += acc1.z; d1.w += acc1.w;
    *(float4*)(out + o) = d0;
    *(float4*)(out + o + 4) = d1;
}

// ---------------- launch ----------------
extern "C" void kernel_launch(void* const* d_in, const int* in_sizes, int n_in,
                              void* d_out, int out_size)
{
    const float* x    = (const float*)d_in[0];
    const float* w    = (const float*)d_in[1];
    const float* bias = (const float*)d_in[2];
    const float* ew   = (const float*)d_in[3];
    const int*   er   = (const int*)d_in[4];
    const int*   ec   = (const int*)d_in[5];
    float* out = (float*)d_out;

    const int M = in_sizes[0] / DCOLS;    // 100000
    const int E = in_sizes[3];            // 3200000

    // 1) dense GEMM + bias epilogue (out = support + bias, g_bufA = support)
    dim3 ggrid(DCOLS / BN, (M + BM - 1) / BM);
    gemm_kernel<<<ggrid, 256>>>(x, w, bias, out, M);

    // 2) CSR build
    zero_counts_kernel<<<(M + 255) / 256, 256>>>(M);
    count_kernel<<<2048, 256>>>(er, E);
    scan_kernel<<<1, 1024>>>(M);
    scatter_kernel<<<2048, 256>>>(er, ec, ew, E);

    // 3) three SpMM rounds (ping-pong), accumulating into out
    const int sblocks = (int)(((size_t)M * 32 + 255) / 256);
    spmm_kernel<<<sblocks, 256>>>(0, out, M);
    spmm_kernel<<<sblocks, 256>>>(1, out, M);
    spmm_kernel<<<sblocks, 256>>>(0, out, M);
}

// round 3
// speedup vs baseline: 2.1382x; 2.1382x over previous
#include <cuda_runtime.h>
#include <cuda_fp16.h>
#include <cstdint>

#define NROWS 100000
#define DCOLS 256
#define NEDGE 3200000

// ---------------- scratch (device globals: allocation-free) ----------------
__device__ float  g_sup32[(size_t)NROWS * DCOLS];   // support, fp32 (for output)
__device__ __half g_s16 [(size_t)NROWS * DCOLS];    // support, fp16 (for gather)
__device__ __half g_h1  [(size_t)NROWS * DCOLS];    // A s
__device__ __half g_h2  [(size_t)NROWS * DCOLS];    // A^2 s
__device__ __half g_h3  [(size_t)NROWS * DCOLS];    // A^3 s
__device__ int    g_counts[NROWS];
__device__ int    g_row_start[NROWS + 1];
__device__ int    g_cursor[NROWS];
__device__ int    g_csr_col[NEDGE];
__device__ float  g_csr_w[NEDGE];
__device__ int    g_blocksums[128];
__device__ int    g_blockoff[128];

// ======================= tf32 tensor-core GEMM =============================
// support = x @ w ;  writes g_sup32 (fp32) and g_s16 (fp16)
#define GBM 128
#define GBN 128
#define GBK 16
#define AST 17   // padded smem stride

__device__ __forceinline__ unsigned f2tf32(float f) {
    unsigned r;
    asm("cvt.rna.tf32.f32 %0, %1;" : "=r"(r) : "f"(f));
    return r;
}

__global__ __launch_bounds__(256) void gemm_tf32_kernel(
    const float* __restrict__ x, const float* __restrict__ w, int M)
{
    __shared__ float As[GBM][AST];
    __shared__ float Bs[GBN][AST];   // transposed: Bs[n][k]

    const int tid = threadIdx.x;
    const int lane = tid & 31;
    const int warp = tid >> 5;
    const int gid = lane >> 2;       // 0..7
    const int tig = lane & 3;        // 0..3

    const int row0 = blockIdx.y * GBM;
    const int col0 = blockIdx.x * GBN;
    const int warp_m = (warp >> 2) * 64;
    const int warp_n = (warp & 3) * 32;

    // A-load mapping: rows r, r+64 ; 4 k each
    const int ar = tid >> 2;             // 0..63
    const int ak = (tid & 3) * 4;
    // B-load mapping: k rows kb, kb+8 ; 4 cols each
    const int kb = tid >> 5;             // 0..7
    const int bc = (tid & 31) * 4;

    float acc[4][4][4];
#pragma unroll
    for (int i = 0; i < 4; i++)
#pragma unroll
        for (int j = 0; j < 4; j++)
#pragma unroll
            for (int q = 0; q < 4; q++) acc[i][j][q] = 0.f;

    for (int k0 = 0; k0 < DCOLS; k0 += GBK) {
        // load A tile (convert to tf32 bits)
#pragma unroll
        for (int h = 0; h < 2; h++) {
            const int r = ar + h * 64;
            const int grow = row0 + r;
            float4 av = make_float4(0.f, 0.f, 0.f, 0.f);
            if (grow < M)
                av = *(const float4*)(x + (size_t)grow * DCOLS + k0 + ak);
            As[r][ak + 0] = __uint_as_float(f2tf32(av.x));
            As[r][ak + 1] = __uint_as_float(f2tf32(av.y));
            As[r][ak + 2] = __uint_as_float(f2tf32(av.z));
            As[r][ak + 3] = __uint_as_float(f2tf32(av.w));
        }
        // load B tile transposed
#pragma unroll
        for (int h = 0; h < 2; h++) {
            const int k = kb + h * 8;
            float4 bv = *(const float4*)(w + (size_t)(k0 + k) * DCOLS + col0 + bc);
            Bs[bc + 0][k] = __uint_as_float(f2tf32(bv.x));
            Bs[bc + 1][k] = __uint_as_float(f2tf32(bv.y));
            Bs[bc + 2][k] = __uint_as_float(f2tf32(bv.z));
            Bs[bc + 3][k] = __uint_as_float(f2tf32(bv.w));
        }
        __syncthreads();

#pragma unroll
        for (int ks = 0; ks < 2; ks++) {
            const int kk = ks * 8;
            unsigned a[4][4], b[4][2];
#pragma unroll
            for (int i = 0; i < 4; i++) {
                const int r = warp_m + i * 16;
                a[i][0] = __float_as_uint(As[r + gid][kk + tig]);
                a[i][1] = __float_as_uint(As[r + gid + 8][kk + tig]);
                a[i][2] = __float_as_uint(As[r + gid][kk + tig + 4]);
                a[i][3] = __float_as_uint(As[r + gid + 8][kk + tig + 4]);
            }
#pragma unroll
            for (int j = 0; j < 4; j++) {
                const int n = warp_n + j * 8 + gid;
                b[j][0] = __float_as_uint(Bs[n][kk + tig]);
                b[j][1] = __float_as_uint(Bs[n][kk + tig + 4]);
            }
#pragma unroll
            for (int i = 0; i < 4; i++)
#pragma unroll
                for (int j = 0; j < 4; j++) {
                    asm volatile(
                        "mma.sync.aligned.m16n8k8.row.col.f32.tf32.tf32.f32 "
                        "{%0,%1,%2,%3}, {%4,%5,%6,%7}, {%8,%9}, {%0,%1,%2,%3};"
                        : "+f"(acc[i][j][0]), "+f"(acc[i][j][1]),
                          "+f"(acc[i][j][2]), "+f"(acc[i][j][3])
                        : "r"(a[i][0]), "r"(a[i][1]), "r"(a[i][2]), "r"(a[i][3]),
                          "r"(b[j][0]), "r"(b[j][1]));
                }
        }
        __syncthreads();
    }

    // epilogue: write fp32 + fp16 copies
#pragma unroll
    for (int i = 0; i < 4; i++) {
#pragma unroll
        for (int h = 0; h < 2; h++) {
            const int r = row0 + warp_m + i * 16 + gid + h * 8;
            if (r < M) {
#pragma unroll
                for (int j = 0; j < 4; j++) {
                    const int c = col0 + warp_n + j * 8 + 2 * tig;
                    const float v0 = acc[i][j][2 * h];
                    const float v1 = acc[i][j][2 * h + 1];
                    *(float2*)(g_sup32 + (size_t)r * DCOLS + c) = make_float2(v0, v1);
                    __half2 hh = __floats2half2_rn(v0, v1);
                    *(__half2*)(g_s16 + (size_t)r * DCOLS + c) = hh;
                }
            }
        }
    }
}

// ======================= CSR build =========================================
__global__ void zero_counts_kernel(int M)
{
    for (int i = blockIdx.x * blockDim.x + threadIdx.x; i < M;
         i += gridDim.x * blockDim.x)
        g_counts[i] = 0;
}

__global__ void count_kernel(const int* __restrict__ erow, int E)
{
    for (int i = blockIdx.x * blockDim.x + threadIdx.x; i < E;
         i += gridDim.x * blockDim.x)
        atomicAdd(&g_counts[erow[i]], 1);
}

// local per-block (1024-elem) exclusive scan
__global__ __launch_bounds__(1024) void local_scan_kernel(int M)
{
    __shared__ int sh[1024];
    const int t = threadIdx.x;
    const int i = blockIdx.x * 1024 + t;
    const int v = (i < M) ? g_counts[i] : 0;
    sh[t] = v;
    __syncthreads();
#pragma unroll
    for (int d = 1; d < 1024; d <<= 1) {
        int u = (t >= d) ? sh[t - d] : 0;
        __syncthreads();
        sh[t] += u;
        __syncthreads();
    }
    if (i < M) g_row_start[i] = sh[t] - v;   // local exclusive
    if (t == 1023) g_blocksums[blockIdx.x] = sh[1023];
}

__global__ __launch_bounds__(128) void scan_sums_kernel(int NB)
{
    __shared__ int sh[128];
    const int t = threadIdx.x;
    const int v = (t < NB) ? g_blocksums[t] : 0;
    sh[t] = v;
    __syncthreads();
#pragma unroll
    for (int d = 1; d < 128; d <<= 1) {
        int u = (t >= d) ? sh[t - d] : 0;
        __syncthreads();
        sh[t] += u;
        __syncthreads();
    }
    g_blockoff[t] = sh[t] - v;               // exclusive
}

__global__ __launch_bounds__(1024) void add_off_kernel(int M, int E)
{
    const int t = threadIdx.x;
    const int i = blockIdx.x * 1024 + t;
    if (i < M) {
        const int rs = g_row_start[i] + g_blockoff[blockIdx.x];
        g_row_start[i] = rs;
        g_cursor[i] = rs;
    }
    if (blockIdx.x == 0 && t == 0) g_row_start[M] = E;
}

__global__ void scatter_kernel(const int* __restrict__ erow,
                               const int* __restrict__ ecol,
                               const float* __restrict__ ew, int E)
{
    for (int i = blockIdx.x * blockDim.x + threadIdx.x; i < E;
         i += gridDim.x * blockDim.x) {
        const int r = erow[i];
        const int pos = atomicAdd(&g_cursor[r], 1);
        g_csr_col[pos] = ecol[i];
        g_csr_w[pos] = ew[i];
    }
}

// ======================= SpMM (fp16 gather, fp32 accum) ====================
__device__ __forceinline__ void acc_edge(float* a, float wgt, uint4 v)
{
    const __half2* h = (const __half2*)&v;
#pragma unroll
    for (int q = 0; q < 4; q++) {
        float2 f = __half22float2(h[q]);
        a[2 * q + 0] = fmaf(wgt, f.x, a[2 * q + 0]);
        a[2 * q + 1] = fmaf(wgt, f.y, a[2 * q + 1]);
    }
}

__device__ __forceinline__ unsigned packh2(float x, float y)
{
    __half2 h = __floats2half2_rn(x, y);
    return *(unsigned*)&h;
}

__global__ __launch_bounds__(256) void spmm_kernel(int stage, int M)
{
    const __half* __restrict__ cur;
    __half* __restrict__ nxt;
    if (stage == 0)      { cur = g_s16; nxt = g_h1; }
    else if (stage == 1) { cur = g_h1;  nxt = g_h2; }
    else                 { cur = g_h2;  nxt = g_h3; }

    const int warp = (blockIdx.x * blockDim.x + threadIdx.x) >> 5;
    if (warp >= M) return;
    const int lane = threadIdx.x & 31;

    const int s = g_row_start[warp];
    const int e = g_row_start[warp + 1];

    float a[8];
#pragma unroll
    for (int q = 0; q < 8; q++) a[q] = 0.f;

    int j = s;
    for (; j + 1 < e; j += 2) {
        const int c0 = g_csr_col[j];
        const int c1 = g_csr_col[j + 1];
        const float w0 = g_csr_w[j];
        const float w1 = g_csr_w[j + 1];
        uint4 v0 = ((const uint4*)(cur + (size_t)c0 * DCOLS))[lane];
        uint4 v1 = ((const uint4*)(cur + (size_t)c1 * DCOLS))[lane];
        acc_edge(a, w0, v0);
        acc_edge(a, w1, v1);
    }
    if (j < e) {
        const int c0 = g_csr_col[j];
        const float w0 = g_csr_w[j];
        uint4 v0 = ((const uint4*)(cur + (size_t)c0 * DCOLS))[lane];
        acc_edge(a, w0, v0);
    }

    uint4 o;
    o.x = packh2(a[0], a[1]);
    o.y = packh2(a[2], a[3]);
    o.z = packh2(a[4], a[5]);
    o.w = packh2(a[6], a[7]);
    ((uint4*)(nxt + (size_t)warp * DCOLS))[lane] = o;
}

// ======================= final combine =====================================
// out = sup32 + h1 + h2 + h3 + bias
__global__ __launch_bounds__(256) void combine_kernel(
    float* __restrict__ out, const float* __restrict__ bias, int M)
{
    const size_t total4 = (size_t)M * (DCOLS / 4);
    for (size_t i = blockIdx.x * blockDim.x + threadIdx.x; i < total4;
         i += (size_t)gridDim.x * blockDim.x) {
        const size_t o = i * 4;
        const int col = (int)(o & (DCOLS - 1));
        float4 s = *(const float4*)(g_sup32 + o);
        float4 bb = *(const float4*)(bias + col);
        const __half2* p1 = (const __half2*)(g_h1 + o);
        const __half2* p2 = (const __half2*)(g_h2 + o);
        const __half2* p3 = (const __half2*)(g_h3 + o);
        float2 a0 = __half22float2(p1[0]), a1 = __half22float2(p1[1]);
        float2 b0 = __half22float2(p2[0]), b1 = __half22float2(p2[1]);
        float2 c0 = __half22float2(p3[0]), c1 = __half22float2(p3[1]);
        s.x += a0.x + b0.x + c0.x + bb.x;
        s.y += a0.y + b0.y + c0.y + bb.y;
        s.z += a1.x + b1.x + c1.x + bb.z;
        s.w += a1.y + b1.y + c1.y + bb.w;
        *(float4*)(out + o) = s;
    }
}

// ======================= launch ============================================
extern "C" void kernel_launch(void* const* d_in, const int* in_sizes, int n_in,
                              void* d_out, int out_size)
{
    const float* x    = (const float*)d_in[0];
    const float* w    = (const float*)d_in[1];
    const float* bias = (const float*)d_in[2];
    const float* ew   = (const float*)d_in[3];
    const int*   er   = (const int*)d_in[4];
    const int*   ec   = (const int*)d_in[5];
    float* out = (float*)d_out;

    const int M = in_sizes[0] / DCOLS;
    const int E = in_sizes[3];
    const int NB = (M + 1023) / 1024;

    // 1) tensor-core GEMM
    dim3 ggrid(DCOLS / GBN, (M + GBM - 1) / GBM);
    gemm_tf32_kernel<<<ggrid, 256>>>(x, w, M);

    // 2) CSR build (parallel scan)
    zero_counts_kernel<<<(M + 255) / 256, 256>>>(M);
    count_kernel<<<2048, 256>>>(er, E);
    local_scan_kernel<<<NB, 1024>>>(M);
    scan_sums_kernel<<<1, 128>>>(NB);
    add_off_kernel<<<NB, 1024>>>(M, E);
    scatter_kernel<<<2048, 256>>>(er, ec, ew, E);

    // 3) three SpMM hops (fp16 buffers)
    const int sblocks = (int)(((size_t)M * 32 + 255) / 256);
    spmm_kernel<<<sblocks, 256>>>(0, M);
    spmm_kernel<<<sblocks, 256>>>(1, M);
    spmm_kernel<<<sblocks, 256>>>(2, M);

    // 4) fused combine
    combine_kernel<<<2048, 256>>>(out, bias, M);
}

// round 4
// speedup vs baseline: 2.2656x; 1.0596x over previous
#include <cuda_runtime.h>
#include <cuda_fp16.h>
#include <cstdint>

#define NROWS 100000
#define DCOLS 256
#define NEDGE 3200000

// ---------------- scratch (device globals: allocation-free) ----------------
__device__ float   g_sup32[(size_t)NROWS * DCOLS];  // support fp32 (for output)
__device__ __half  g_s16 [(size_t)NROWS * DCOLS];   // support fp16 (hop1 gather)
__device__ __half  g_h1  [(size_t)NROWS * DCOLS];   // A s   (fp16)
__device__ __half  g_h2  [(size_t)NROWS * DCOLS];   // A^2 s (fp16, for output)
__device__ unsigned char g_h2q[(size_t)NROWS * DCOLS]; // A^2 s * 256 (e4m3, hop3 gather)
__device__ int     g_counts[NROWS];
__device__ int     g_row_start[NROWS + 1];
__device__ int     g_cursor[NROWS];
__device__ int     g_csr_col[NEDGE];
__device__ float   g_csr_w[NEDGE];
__device__ int     g_blocksums[128];
__device__ int     g_blockoff[128];

// ======================= fp16 tensor-core GEMM =============================
// support = x @ w ; writes g_sup32 (fp32) and g_s16 (fp16)
#define GBM 128
#define GBN 128
#define GBK 32
#define HST 40   // padded smem stride (halves)

__global__ __launch_bounds__(256) void gemm_f16_kernel(
    const float* __restrict__ x, const float* __restrict__ w, int M)
{
    __shared__ __half As[GBM][HST];
    __shared__ __half Bs[GBN][HST];   // transposed: Bs[n][k]

    const int tid  = threadIdx.x;
    const int lane = tid & 31;
    const int warp = tid >> 5;
    const int gid  = lane >> 2;       // 0..7
    const int tig  = lane & 3;        // 0..3

    const int row0 = blockIdx.y * GBM;
    const int col0 = blockIdx.x * GBN;
    const int warp_m = (warp >> 2) * 64;
    const int warp_n = (warp & 3) * 32;

    float acc[4][4][4];
#pragma unroll
    for (int i = 0; i < 4; i++)
#pragma unroll
        for (int j = 0; j < 4; j++)
#pragma unroll
            for (int q = 0; q < 4; q++) acc[i][j][q] = 0.f;

    for (int k0 = 0; k0 < DCOLS; k0 += GBK) {
        // A tile: 128 rows x 32 k (1024 float4 chunks, 4 per thread)
#pragma unroll
        for (int h = 0; h < 4; h++) {
            const int idx = tid + h * 256;
            const int r  = idx >> 3;          // 0..127
            const int kc = (idx & 7) * 4;     // 0..28
            const int grow = row0 + r;
            float4 av = make_float4(0.f, 0.f, 0.f, 0.f);
            if (grow < M)
                av = *(const float4*)(x + (size_t)grow * DCOLS + k0 + kc);
            *(__half2*)&As[r][kc]     = __floats2half2_rn(av.x, av.y);
            *(__half2*)&As[r][kc + 2] = __floats2half2_rn(av.z, av.w);
        }
        // B tile transposed: 32 k-rows x 128 cols
#pragma unroll
        for (int h = 0; h < 4; h++) {
            const int idx = tid + h * 256;
            const int k  = idx >> 5;          // 0..31
            const int nc = (idx & 31) * 4;    // 0..124
            float4 bv = *(const float4*)(w + (size_t)(k0 + k) * DCOLS + col0 + nc);
            Bs[nc + 0][k] = __float2half_rn(bv.x);
            Bs[nc + 1][k] = __float2half_rn(bv.y);
            Bs[nc + 2][k] = __float2half_rn(bv.z);
            Bs[nc + 3][k] = __float2half_rn(bv.w);
        }
        __syncthreads();

#pragma unroll
        for (int ks = 0; ks < 2; ks++) {
            const int kk = ks * 16;
            unsigned a[4][4], b[4][2];
#pragma unroll
            for (int i = 0; i < 4; i++) {
                const int rm = warp_m + i * 16;
                a[i][0] = *(const unsigned*)&As[rm + gid    ][kk + 2 * tig];
                a[i][1] = *(const unsigned*)&As[rm + gid + 8][kk + 2 * tig];
                a[i][2] = *(const unsigned*)&As[rm + gid    ][kk + 8 + 2 * tig];
                a[i][3] = *(const unsigned*)&As[rm + gid + 8][kk + 8 + 2 * tig];
            }
#pragma unroll
            for (int j = 0; j < 4; j++) {
                const int n = warp_n + j * 8 + gid;
                b[j][0] = *(const unsigned*)&Bs[n][kk + 2 * tig];
                b[j][1] = *(const unsigned*)&Bs[n][kk + 8 + 2 * tig];
            }
#pragma unroll
            for (int i = 0; i < 4; i++)
#pragma unroll
                for (int j = 0; j < 4; j++) {
                    asm volatile(
                        "mma.sync.aligned.m16n8k16.row.col.f32.f16.f16.f32 "
                        "{%0,%1,%2,%3}, {%4,%5,%6,%7}, {%8,%9}, {%0,%1,%2,%3};"
                        : "+f"(acc[i][j][0]), "+f"(acc[i][j][1]),
                          "+f"(acc[i][j][2]), "+f"(acc[i][j][3])
                        : "r"(a[i][0]), "r"(a[i][1]), "r"(a[i][2]), "r"(a[i][3]),
                          "r"(b[j][0]), "r"(b[j][1]));
                }
        }
        __syncthreads();
    }

    // epilogue: write fp32 + fp16 copies
#pragma unroll
    for (int i = 0; i < 4; i++) {
#pragma unroll
        for (int h = 0; h < 2; h++) {
            const int r = row0 + warp_m + i * 16 + gid + h * 8;
            if (r < M) {
#pragma unroll
                for (int j = 0; j < 4; j++) {
                    const int c = col0 + warp_n + j * 8 + 2 * tig;
                    const float v0 = acc[i][j][2 * h];
                    const float v1 = acc[i][j][2 * h + 1];
                    *(float2*)(g_sup32 + (size_t)r * DCOLS + c) = make_float2(v0, v1);
                    *(__half2*)(g_s16 + (size_t)r * DCOLS + c) = __floats2half2_rn(v0, v1);
                }
            }
        }
    }
}

// ======================= CSR build =========================================
__global__ void zero_counts_kernel(int M)
{
    for (int i = blockIdx.x * blockDim.x + threadIdx.x; i < M;
         i += gridDim.x * blockDim.x)
        g_counts[i] = 0;
}

__global__ void count_kernel(const int* __restrict__ erow, int E)
{
    for (int i = blockIdx.x * blockDim.x + threadIdx.x; i < E;
         i += gridDim.x * blockDim.x)
        atomicAdd(&g_counts[erow[i]], 1);
}

__global__ __launch_bounds__(1024) void local_scan_kernel(int M)
{
    __shared__ int sh[1024];
    const int t = threadIdx.x;
    const int i = blockIdx.x * 1024 + t;
    const int v = (i < M) ? g_counts[i] : 0;
    sh[t] = v;
    __syncthreads();
#pragma unroll
    for (int d = 1; d < 1024; d <<= 1) {
        int u = (t >= d) ? sh[t - d] : 0;
        __syncthreads();
        sh[t] += u;
        __syncthreads();
    }
    if (i < M) g_row_start[i] = sh[t] - v;
    if (t == 1023) g_blocksums[blockIdx.x] = sh[1023];
}

__global__ __launch_bounds__(128) void scan_sums_kernel(int NB)
{
    __shared__ int sh[128];
    const int t = threadIdx.x;
    const int v = (t < NB) ? g_blocksums[t] : 0;
    sh[t] = v;
    __syncthreads();
#pragma unroll
    for (int d = 1; d < 128; d <<= 1) {
        int u = (t >= d) ? sh[t - d] : 0;
        __syncthreads();
        sh[t] += u;
        __syncthreads();
    }
    g_blockoff[t] = sh[t] - v;
}

__global__ __launch_bounds__(1024) void add_off_kernel(int M, int E)
{
    const int t = threadIdx.x;
    const int i = blockIdx.x * 1024 + t;
    if (i < M) {
        const int rs = g_row_start[i] + g_blockoff[blockIdx.x];
        g_row_start[i] = rs;
        g_cursor[i] = rs;
    }
    if (blockIdx.x == 0 && t == 0) g_row_start[M] = E;
}

__global__ void scatter_kernel(const int* __restrict__ erow,
                               const int* __restrict__ ecol,
                               const float* __restrict__ ew, int E)
{
    for (int i = blockIdx.x * blockDim.x + threadIdx.x; i < E;
         i += gridDim.x * blockDim.x) {
        const int r = erow[i];
        const int pos = atomicAdd(&g_cursor[r], 1);
        g_csr_col[pos] = ecol[i];
        g_csr_w[pos] = ew[i];
    }
}

// ======================= fp8 helpers =======================================
__device__ __forceinline__ __half2 fp8x2_to_h2(unsigned short v)
{
    unsigned r;
    asm("cvt.rn.f16x2.e4m3x2 %0, %1;" : "=r"(r) : "h"(v));
    return *(__half2*)&r;
}

__device__ __forceinline__ unsigned short f2_to_fp8x2(float lo, float hi)
{
    unsigned short r;
    asm("cvt.rn.satfinite.e4m3x2.f32 %0, %1, %2;" : "=h"(r) : "f"(hi), "f"(lo));
    return r;
}

// ======================= SpMM hops =========================================
__device__ __forceinline__ void acc_edge(float* a, float wgt, uint4 v)
{
    const __half2* h = (const __half2*)&v;
#pragma unroll
    for (int q = 0; q < 4; q++) {
        float2 f = __half22float2(h[q]);
        a[2 * q + 0] = fmaf(wgt, f.x, a[2 * q + 0]);
        a[2 * q + 1] = fmaf(wgt, f.y, a[2 * q + 1]);
    }
}

__device__ __forceinline__ unsigned packh2(float x, float y)
{
    __half2 h = __floats2half2_rn(x, y);
    return *(unsigned*)&h;
}

// generic fp16-gather loop into a[8]
#define GATHER_FP16(cur, s, e, lane, a)                                     \
    {                                                                       \
        int j = (s);                                                        \
        for (; j + 1 < (e); j += 2) {                                       \
            const int c0 = g_csr_col[j];                                    \
            const int c1 = g_csr_col[j + 1];                                \
            const float w0 = g_csr_w[j];                                    \
            const float w1 = g_csr_w[j + 1];                                \
            uint4 v0 = ((const uint4*)((cur) + (size_t)c0 * DCOLS))[lane];  \
            uint4 v1 = ((const uint4*)((cur) + (size_t)c1 * DCOLS))[lane];  \
            acc_edge(a, w0, v0);                                            \
            acc_edge(a, w1, v1);                                            \
        }                                                                   \
        if (j < (e)) {                                                      \
            const int c0 = g_csr_col[j];                                    \
            const float w0 = g_csr_w[j];                                    \
            uint4 v0 = ((const uint4*)((cur) + (size_t)c0 * DCOLS))[lane];  \
            acc_edge(a, w0, v0);                                            \
        }                                                                   \
    }

// hop1: h1 = A * s16
__global__ __launch_bounds__(256) void spmm1_kernel(int M)
{
    const int warp = (blockIdx.x * blockDim.x + threadIdx.x) >> 5;
    if (warp >= M) return;
    const int lane = threadIdx.x & 31;
    const int s = g_row_start[warp];
    const int e = g_row_start[warp + 1];

    float a[8];
#pragma unroll
    for (int q = 0; q < 8; q++) a[q] = 0.f;
    GATHER_FP16(g_s16, s, e, lane, a);

    uint4 o;
    o.x = packh2(a[0], a[1]); o.y = packh2(a[2], a[3]);
    o.z = packh2(a[4], a[5]); o.w = packh2(a[6], a[7]);
    ((uint4*)(g_h1 + (size_t)warp * DCOLS))[lane] = o;
}

// hop2: h2 = A * h1 ; writes fp16 h2 and fp8 (x256) copy for hop3
__global__ __launch_bounds__(256) void spmm2_kernel(int M)
{
    const int warp = (blockIdx.x * blockDim.x + threadIdx.x) >> 5;
    if (warp >= M) return;
    const int lane = threadIdx.x & 31;
    const int s = g_row_start[warp];
    const int e = g_row_start[warp + 1];

    float a[8];
#pragma unroll
    for (int q = 0; q < 8; q++) a[q] = 0.f;
    GATHER_FP16(g_h1, s, e, lane, a);

    uint4 o;
    o.x = packh2(a[0], a[1]); o.y = packh2(a[2], a[3]);
    o.z = packh2(a[4], a[5]); o.w = packh2(a[6], a[7]);
    ((uint4*)(g_h2 + (size_t)warp * DCOLS))[lane] = o;

    ushort4 q8;
    q8.x = f2_to_fp8x2(a[0] * 256.f, a[1] * 256.f);
    q8.y = f2_to_fp8x2(a[2] * 256.f, a[3] * 256.f);
    q8.z = f2_to_fp8x2(a[4] * 256.f, a[5] * 256.f);
    q8.w = f2_to_fp8x2(a[6] * 256.f, a[7] * 256.f);
    ((ushort4*)(g_h2q + (size_t)warp * DCOLS))[lane] = q8;
}

// hop3 fused with combine: out = sup32 + h1 + h2 + (A*h2q)/256 + bias
__global__ __launch_bounds__(256) void spmm3_combine_kernel(
    float* __restrict__ out, const float* __restrict__ bias, int M)
{
    const int warp = (blockIdx.x * blockDim.x + threadIdx.x) >> 5;
    if (warp >= M) return;
    const int lane = threadIdx.x & 31;
    const int s = g_row_start[warp];
    const int e = g_row_start[warp + 1];

    float a[8];
#pragma unroll
    for (int q = 0; q < 8; q++) a[q] = 0.f;

    // fp8 gather: 8 bytes per lane per row
    int j = s;
    for (; j + 1 < e; j += 2) {
        const int c0 = g_csr_col[j];
        const int c1 = g_csr_col[j + 1];
        const float w0 = g_csr_w[j];
        const float w1 = g_csr_w[j + 1];
        uint2 v0 = ((const uint2*)(g_h2q + (size_t)c0 * DCOLS))[lane];
        uint2 v1 = ((const uint2*)(g_h2q + (size_t)c1 * DCOLS))[lane];
        const unsigned short* p0 = (const unsigned short*)&v0;
        const unsigned short* p1 = (const unsigned short*)&v1;
#pragma unroll
        for (int q = 0; q < 4; q++) {
            float2 f0 = __half22float2(fp8x2_to_h2(p0[q]));
            float2 f1 = __half22float2(fp8x2_to_h2(p1[q]));
            a[2 * q + 0] = fmaf(w0, f0.x, fmaf(w1, f1.x, a[2 * q + 0]));
            a[2 * q + 1] = fmaf(w0, f0.y, fmaf(w1, f1.y, a[2 * q + 1]));
        }
    }
    if (j < e) {
        const int c0 = g_csr_col[j];
        const float w0 = g_csr_w[j];
        uint2 v0 = ((const uint2*)(g_h2q + (size_t)c0 * DCOLS))[lane];
        const unsigned short* p0 = (const unsigned short*)&v0;
#pragma unroll
        for (int q = 0; q < 4; q++) {
            float2 f0 = __half22float2(fp8x2_to_h2(p0[q]));
            a[2 * q + 0] = fmaf(w0, f0.x, a[2 * q + 0]);
            a[2 * q + 1] = fmaf(w0, f0.y, a[2 * q + 1]);
        }
    }

    const size_t o = (size_t)warp * DCOLS + lane * 8;
    float4 s0 = *(const float4*)(g_sup32 + o);
    float4 s1 = *(const float4*)(g_sup32 + o + 4);
    float4 b0 = *(const float4*)(bias + lane * 8);
    float4 b1 = *(const float4*)(bias + lane * 8 + 4);
    uint4 u1 = ((const uint4*)(g_h1 + (size_t)warp * DCOLS))[lane];
    uint4 u2 = ((const uint4*)(g_h2 + (size_t)warp * DCOLS))[lane];
    const __half2* h1 = (const __half2*)&u1;
    const __half2* h2 = (const __half2*)&u2;

    float r[8];
#pragma unroll
    for (int q = 0; q < 4; q++) {
        float2 f1 = __half22float2(h1[q]);
        float2 f2 = __half22float2(h2[q]);
        r[2 * q + 0] = f1.x + f2.x + a[2 * q + 0] * (1.f / 256.f);
        r[2 * q + 1] = f1.y + f2.y + a[2 * q + 1] * (1.f / 256.f);
    }
    float4 o0 = make_float4(s0.x + r[0] + b0.x, s0.y + r[1] + b0.y,
                            s0.z + r[2] + b0.z, s0.w + r[3] + b0.w);
    float4 o1 = make_float4(s1.x + r[4] + b1.x, s1.y + r[5] + b1.y,
                            s1.z + r[6] + b1.z, s1.w + r[7] + b1.w);
    *(float4*)(out + o) = o0;
    *(float4*)(out + o + 4) = o1;
}

// ======================= launch ============================================
extern "C" void kernel_launch(void* const* d_in, const int* in_sizes, int n_in,
                              void* d_out, int out_size)
{
    const float* x    = (const float*)d_in[0];
    const float* w    = (const float*)d_in[1];
    const float* bias = (const float*)d_in[2];
    const float* ew   = (const float*)d_in[3];
    const int*   er   = (const int*)d_in[4];
    const int*   ec   = (const int*)d_in[5];
    float* out = (float*)d_out;

    const int M = in_sizes[0] / DCOLS;
    const int E = in_sizes[3];
    const int NB = (M + 1023) / 1024;

    // 1) fp16 tensor-core GEMM
    dim3 ggrid(DCOLS / GBN, (M + GBM - 1) / GBM);
    gemm_f16_kernel<<<ggrid, 256>>>(x, w, M);

    // 2) CSR build (parallel scan)
    zero_counts_kernel<<<(M + 255) / 256, 256>>>(M);
    count_kernel<<<2048, 256>>>(er, E);
    local_scan_kernel<<<NB, 1024>>>(M);
    scan_sums_kernel<<<1, 128>>>(NB);
    add_off_kernel<<<NB, 1024>>>(M, E);
    scatter_kernel<<<2048, 256>>>(er, ec, ew, E);

    // 3) hops: fp16, fp16(+fp8 copy), fp8 fused with combine
    const int sblocks = (int)(((size_t)M * 32 + 255) / 256);
    spmm1_kernel<<<sblocks, 256>>>(M);
    spmm2_kernel<<<sblocks, 256>>>(M);
    spmm3_combine_kernel<<<sblocks, 256>>>(out, bias, M);
}

// round 5
// speedup vs baseline: 2.3852x; 1.0528x over previous
#include <cuda_runtime.h>
#include <cuda_fp16.h>
#include <cstdint>

#define NROWS 100000
#define DCOLS 256
#define NEDGE 3200000

// ---------------- scratch (device globals: allocation-free) ----------------
__device__ float   g_sup32[(size_t)NROWS * DCOLS];  // support fp32 (for output)
__device__ __half  g_s16 [(size_t)NROWS * DCOLS];   // support fp16 (hop1 gather)
__device__ __half  g_h1  [(size_t)NROWS * DCOLS];   // A s   fp16 (output term)
__device__ __half  g_h2  [(size_t)NROWS * DCOLS];   // A^2 s fp16 (output term)
__device__ unsigned char g_h1q[(size_t)NROWS * DCOLS]; // h1 * 16  (e4m3, hop2 gather)
__device__ unsigned char g_h2q[(size_t)NROWS * DCOLS]; // h2 * 256 (e4m3, hop3 gather)
__device__ int     g_counts[NROWS];
__device__ int     g_row_start[NROWS + 1];
__device__ int     g_cursor[NROWS];
__device__ int2    g_csr[NEDGE];          // (col, weight bits) interleaved
__device__ int     g_blocksums[128];
__device__ int     g_blockoff[128];

// ======================= fp16 tensor-core GEMM =============================
#define GBM 128
#define GBN 128
#define GBK 32
#define HST 40   // padded smem stride (halves)

__global__ __launch_bounds__(256) void gemm_f16_kernel(
    const float* __restrict__ x, const float* __restrict__ w, int M)
{
    __shared__ __half As[GBM][HST];
    __shared__ __half Bs[GBN][HST];   // transposed: Bs[n][k]

    const int tid  = threadIdx.x;
    const int lane = tid & 31;
    const int warp = tid >> 5;
    const int gid  = lane >> 2;       // 0..7
    const int tig  = lane & 3;        // 0..3

    const int row0 = blockIdx.y * GBM;
    const int col0 = blockIdx.x * GBN;
    const int warp_m = (warp >> 2) * 64;
    const int warp_n = (warp & 3) * 32;

    // per-thread load coordinates
    int a_r[4], a_k[4], b_k[4], b_n[4];
#pragma unroll
    for (int h = 0; h < 4; h++) {
        const int idx = tid + h * 256;
        a_r[h] = idx >> 3;            // 0..127
        a_k[h] = (idx & 7) * 4;       // 0..28
        b_k[h] = idx >> 5;            // 0..31
        b_n[h] = (idx & 31) * 4;      // 0..124
    }

    float acc[4][4][4];
#pragma unroll
    for (int i = 0; i < 4; i++)
#pragma unroll
        for (int j = 0; j < 4; j++)
#pragma unroll
            for (int q = 0; q < 4; q++) acc[i][j][q] = 0.f;

    float4 ap[4], bp[4];
    // prefetch k0 = 0
#pragma unroll
    for (int h = 0; h < 4; h++) {
        const int grow = row0 + a_r[h];
        ap[h] = make_float4(0.f, 0.f, 0.f, 0.f);
        if (grow < M)
            ap[h] = *(const float4*)(x + (size_t)grow * DCOLS + a_k[h]);
        bp[h] = *(const float4*)(w + (size_t)b_k[h] * DCOLS + col0 + b_n[h]);
    }

    for (int k0 = 0; k0 < DCOLS; k0 += GBK) {
        // commit prefetched tile to smem
#pragma unroll
        for (int h = 0; h < 4; h++) {
            *(__half2*)&As[a_r[h]][a_k[h]]     = __floats2half2_rn(ap[h].x, ap[h].y);
            *(__half2*)&As[a_r[h]][a_k[h] + 2] = __floats2half2_rn(ap[h].z, ap[h].w);
            Bs[b_n[h] + 0][b_k[h]] = __float2half_rn(bp[h].x);
            Bs[b_n[h] + 1][b_k[h]] = __float2half_rn(bp[h].y);
            Bs[b_n[h] + 2][b_k[h]] = __float2half_rn(bp[h].z);
            Bs[b_n[h] + 3][b_k[h]] = __float2half_rn(bp[h].w);
        }
        __syncthreads();

        // prefetch next tile while doing mma
        const int kn = k0 + GBK;
        if (kn < DCOLS) {
#pragma unroll
            for (int h = 0; h < 4; h++) {
                const int grow = row0 + a_r[h];
                ap[h] = make_float4(0.f, 0.f, 0.f, 0.f);
                if (grow < M)
                    ap[h] = *(const float4*)(x + (size_t)grow * DCOLS + kn + a_k[h]);
                bp[h] = *(const float4*)(w + (size_t)(kn + b_k[h]) * DCOLS + col0 + b_n[h]);
            }
        }

#pragma unroll
        for (int ks = 0; ks < 2; ks++) {
            const int kk = ks * 16;
            unsigned a[4][4], b[4][2];
#pragma unroll
            for (int i = 0; i < 4; i++) {
                const int rm = warp_m + i * 16;
                a[i][0] = *(const unsigned*)&As[rm + gid    ][kk + 2 * tig];
                a[i][1] = *(const unsigned*)&As[rm + gid + 8][kk + 2 * tig];
                a[i][2] = *(const unsigned*)&As[rm + gid    ][kk + 8 + 2 * tig];
                a[i][3] = *(const unsigned*)&As[rm + gid + 8][kk + 8 + 2 * tig];
            }
#pragma unroll
            for (int j = 0; j < 4; j++) {
                const int n = warp_n + j * 8 + gid;
                b[j][0] = *(const unsigned*)&Bs[n][kk + 2 * tig];
                b[j][1] = *(const unsigned*)&Bs[n][kk + 8 + 2 * tig];
            }
#pragma unroll
            for (int i = 0; i < 4; i++)
#pragma unroll
                for (int j = 0; j < 4; j++) {
                    asm volatile(
                        "mma.sync.aligned.m16n8k16.row.col.f32.f16.f16.f32 "
                        "{%0,%1,%2,%3}, {%4,%5,%6,%7}, {%8,%9}, {%0,%1,%2,%3};"
                        : "+f"(acc[i][j][0]), "+f"(acc[i][j][1]),
                          "+f"(acc[i][j][2]), "+f"(acc[i][j][3])
                        : "r"(a[i][0]), "r"(a[i][1]), "r"(a[i][2]), "r"(a[i][3]),
                          "r"(b[j][0]), "r"(b[j][1]));
                }
        }
        __syncthreads();
    }

    // epilogue: write fp32 + fp16 copies
#pragma unroll
    for (int i = 0; i < 4; i++) {
#pragma unroll
        for (int h = 0; h < 2; h++) {
            const int r = row0 + warp_m + i * 16 + gid + h * 8;
            if (r < M) {
#pragma unroll
                for (int j = 0; j < 4; j++) {
                    const int c = col0 + warp_n + j * 8 + 2 * tig;
                    const float v0 = acc[i][j][2 * h];
                    const float v1 = acc[i][j][2 * h + 1];
                    *(float2*)(g_sup32 + (size_t)r * DCOLS + c) = make_float2(v0, v1);
                    *(__half2*)(g_s16 + (size_t)r * DCOLS + c) = __floats2half2_rn(v0, v1);
                }
            }
        }
    }
}

// ======================= CSR build =========================================
__global__ void zero_counts_kernel(int M)
{
    for (int i = blockIdx.x * blockDim.x + threadIdx.x; i < M;
         i += gridDim.x * blockDim.x)
        g_counts[i] = 0;
}

__global__ void count_kernel(const int* __restrict__ erow, int E)
{
    for (int i = blockIdx.x * blockDim.x + threadIdx.x; i < E;
         i += gridDim.x * blockDim.x)
        atomicAdd(&g_counts[erow[i]], 1);
}

__global__ __launch_bounds__(1024) void local_scan_kernel(int M)
{
    __shared__ int sh[1024];
    const int t = threadIdx.x;
    const int i = blockIdx.x * 1024 + t;
    const int v = (i < M) ? g_counts[i] : 0;
    sh[t] = v;
    __syncthreads();
#pragma unroll
    for (int d = 1; d < 1024; d <<= 1) {
        int u = (t >= d) ? sh[t - d] : 0;
        __syncthreads();
        sh[t] += u;
        __syncthreads();
    }
    if (i < M) g_row_start[i] = sh[t] - v;
    if (t == 1023) g_blocksums[blockIdx.x] = sh[1023];
}

__global__ __launch_bounds__(128) void scan_sums_kernel(int NB)
{
    __shared__ int sh[128];
    const int t = threadIdx.x;
    const int v = (t < NB) ? g_blocksums[t] : 0;
    sh[t] = v;
    __syncthreads();
#pragma unroll
    for (int d = 1; d < 128; d <<= 1) {
        int u = (t >= d) ? sh[t - d] : 0;
        __syncthreads();
        sh[t] += u;
        __syncthreads();
    }
    g_blockoff[t] = sh[t] - v;
}

__global__ __launch_bounds__(1024) void add_off_kernel(int M, int E)
{
    const int t = threadIdx.x;
    const int i = blockIdx.x * 1024 + t;
    if (i < M) {
        const int rs = g_row_start[i] + g_blockoff[blockIdx.x];
        g_row_start[i] = rs;
        g_cursor[i] = rs;
    }
    if (blockIdx.x == 0 && t == 0) g_row_start[M] = E;
}

__global__ void scatter_kernel(const int* __restrict__ erow,
                               const int* __restrict__ ecol,
                               const float* __restrict__ ew, int E)
{
    for (int i = blockIdx.x * blockDim.x + threadIdx.x; i < E;
         i += gridDim.x * blockDim.x) {
        const int r = erow[i];
        const int pos = atomicAdd(&g_cursor[r], 1);
        g_csr[pos] = make_int2(ecol[i], __float_as_int(ew[i]));
    }
}

// ======================= fp8 helpers =======================================
__device__ __forceinline__ __half2 fp8x2_to_h2(unsigned short v)
{
    unsigned r;
    asm("cvt.rn.f16x2.e4m3x2 %0, %1;" : "=r"(r) : "h"(v));
    return *(__half2*)&r;
}

__device__ __forceinline__ unsigned short f2_to_fp8x2(float lo, float hi)
{
    unsigned short r;
    asm("cvt.rn.satfinite.e4m3x2.f32 %0, %1, %2;" : "=h"(r) : "f"(hi), "f"(lo));
    return r;
}

// ======================= SpMM hops =========================================
__device__ __forceinline__ void acc_h16(float* a, float wgt, uint4 v)
{
    const __half2* h = (const __half2*)&v;
#pragma unroll
    for (int q = 0; q < 4; q++) {
        float2 f = __half22float2(h[q]);
        a[2 * q + 0] = fmaf(wgt, f.x, a[2 * q + 0]);
        a[2 * q + 1] = fmaf(wgt, f.y, a[2 * q + 1]);
    }
}

__device__ __forceinline__ void acc_q8(float* a, float wgt, uint2 v)
{
    const unsigned short* p = (const unsigned short*)&v;
#pragma unroll
    for (int q = 0; q < 4; q++) {
        float2 f = __half22float2(fp8x2_to_h2(p[q]));
        a[2 * q + 0] = fmaf(wgt, f.x, a[2 * q + 0]);
        a[2 * q + 1] = fmaf(wgt, f.y, a[2 * q + 1]);
    }
}

__device__ __forceinline__ unsigned packh2(float x, float y)
{
    __half2 h = __floats2half2_rn(x, y);
    return *(unsigned*)&h;
}

// hop1: h1 = A * s16 (fp16 gather); writes h1 fp16 + h1q fp8(x16)
__global__ __launch_bounds__(256) void spmm1_kernel(int M)
{
    const int warp = (blockIdx.x * blockDim.x + threadIdx.x) >> 5;
    if (warp >= M) return;
    const int lane = threadIdx.x & 31;
    const int s = g_row_start[warp];
    const int e = g_row_start[warp + 1];

    float a[8];
#pragma unroll
    for (int q = 0; q < 8; q++) a[q] = 0.f;

    int j = s;
    for (; j + 3 < e; j += 4) {
        int2 c0 = g_csr[j], c1 = g_csr[j + 1], c2 = g_csr[j + 2], c3 = g_csr[j + 3];
        uint4 v0 = ((const uint4*)(g_s16 + (size_t)c0.x * DCOLS))[lane];
        uint4 v1 = ((const uint4*)(g_s16 + (size_t)c1.x * DCOLS))[lane];
        uint4 v2 = ((const uint4*)(g_s16 + (size_t)c2.x * DCOLS))[lane];
        uint4 v3 = ((const uint4*)(g_s16 + (size_t)c3.x * DCOLS))[lane];
        acc_h16(a, __int_as_float(c0.y), v0);
        acc_h16(a, __int_as_float(c1.y), v1);
        acc_h16(a, __int_as_float(c2.y), v2);
        acc_h16(a, __int_as_float(c3.y), v3);
    }
    for (; j < e; j++) {
        int2 c0 = g_csr[j];
        uint4 v0 = ((const uint4*)(g_s16 + (size_t)c0.x * DCOLS))[lane];
        acc_h16(a, __int_as_float(c0.y), v0);
    }

    uint4 o;
    o.x = packh2(a[0], a[1]); o.y = packh2(a[2], a[3]);
    o.z = packh2(a[4], a[5]); o.w = packh2(a[6], a[7]);
    ((uint4*)(g_h1 + (size_t)warp * DCOLS))[lane] = o;

    ushort4 q8;
    q8.x = f2_to_fp8x2(a[0] * 16.f, a[1] * 16.f);
    q8.y = f2_to_fp8x2(a[2] * 16.f, a[3] * 16.f);
    q8.z = f2_to_fp8x2(a[4] * 16.f, a[5] * 16.f);
    q8.w = f2_to_fp8x2(a[6] * 16.f, a[7] * 16.f);
    ((ushort4*)(g_h1q + (size_t)warp * DCOLS))[lane] = q8;
}

// hop2: gathers h1q (fp8, = h1*16); a = 16*h2. writes h2 fp16 + h2q fp8(=h2*256)
__global__ __launch_bounds__(256) void spmm2_kernel(int M)
{
    const int warp = (blockIdx.x * blockDim.x + threadIdx.x) >> 5;
    if (warp >= M) return;
    const int lane = threadIdx.x & 31;
    const int s = g_row_start[warp];
    const int e = g_row_start[warp + 1];

    float a[8];
#pragma unroll
    for (int q = 0; q < 8; q++) a[q] = 0.f;

    int j = s;
    for (; j + 3 < e; j += 4) {
        int2 c0 = g_csr[j], c1 = g_csr[j + 1], c2 = g_csr[j + 2], c3 = g_csr[j + 3];
        uint2 v0 = ((const uint2*)(g_h1q + (size_t)c0.x * DCOLS))[lane];
        uint2 v1 = ((const uint2*)(g_h1q + (size_t)c1.x * DCOLS))[lane];
        uint2 v2 = ((const uint2*)(g_h1q + (size_t)c2.x * DCOLS))[lane];
        uint2 v3 = ((const uint2*)(g_h1q + (size_t)c3.x * DCOLS))[lane];
        acc_q8(a, __int_as_float(c0.y), v0);
        acc_q8(a, __int_as_float(c1.y), v1);
        acc_q8(a, __int_as_float(c2.y), v2);
        acc_q8(a, __int_as_float(c3.y), v3);
    }
    for (; j < e; j++) {
        int2 c0 = g_csr[j];
        uint2 v0 = ((const uint2*)(g_h1q + (size_t)c0.x * DCOLS))[lane];
        acc_q8(a, __int_as_float(c0.y), v0);
    }

    // a = 16 * h2
    uint4 o;
    o.x = packh2(a[0] * 0.0625f, a[1] * 0.0625f);
    o.y = packh2(a[2] * 0.0625f, a[3] * 0.0625f);
    o.z = packh2(a[4] * 0.0625f, a[5] * 0.0625f);
    o.w = packh2(a[6] * 0.0625f, a[7] * 0.0625f);
    ((uint4*)(g_h2 + (size_t)warp * DCOLS))[lane] = o;

    ushort4 q8;  // h2*256 = a*16
    q8.x = f2_to_fp8x2(a[0] * 16.f, a[1] * 16.f);
    q8.y = f2_to_fp8x2(a[2] * 16.f, a[3] * 16.f);
    q8.z = f2_to_fp8x2(a[4] * 16.f, a[5] * 16.f);
    q8.w = f2_to_fp8x2(a[6] * 16.f, a[7] * 16.f);
    ((ushort4*)(g_h2q + (size_t)warp * DCOLS))[lane] = q8;
}

// hop3 fused with combine: out = sup32 + h1 + h2 + (A*h2q)/256 + bias
__global__ __launch_bounds__(256) void spmm3_combine_kernel(
    float* __restrict__ out, const float* __restrict__ bias, int M)
{
    const int warp = (blockIdx.x * blockDim.x + threadIdx.x) >> 5;
    if (warp >= M) return;
    const int lane = threadIdx.x & 31;
    const int s = g_row_start[warp];
    const int e = g_row_start[warp + 1];

    float a[8];
#pragma unroll
    for (int q = 0; q < 8; q++) a[q] = 0.f;

    int j = s;
    for (; j + 3 < e; j += 4) {
        int2 c0 = g_csr[j], c1 = g_csr[j + 1], c2 = g_csr[j + 2], c3 = g_csr[j + 3];
        uint2 v0 = ((const uint2*)(g_h2q + (size_t)c0.x * DCOLS))[lane];
        uint2 v1 = ((const uint2*)(g_h2q + (size_t)c1.x * DCOLS))[lane];
        uint2 v2 = ((const uint2*)(g_h2q + (size_t)c2.x * DCOLS))[lane];
        uint2 v3 = ((const uint2*)(g_h2q + (size_t)c3.x * DCOLS))[lane];
        acc_q8(a, __int_as_float(c0.y), v0);
        acc_q8(a, __int_as_float(c1.y), v1);
        acc_q8(a, __int_as_float(c2.y), v2);
        acc_q8(a, __int_as_float(c3.y), v3);
    }
    for (; j < e; j++) {
        int2 c0 = g_csr[j];
        uint2 v0 = ((const uint2*)(g_h2q + (size_t)c0.x * DCOLS))[lane];
        acc_q8(a, __int_as_float(c0.y), v0);
    }

    const size_t o = (size_t)warp * DCOLS + lane * 8;
    float4 s0 = *(const float4*)(g_sup32 + o);
    float4 s1 = *(const float4*)(g_sup32 + o + 4);
    float4 b0 = *(const float4*)(bias + lane * 8);
    float4 b1 = *(const float4*)(bias + lane * 8 + 4);
    uint4 u1 = ((const uint4*)(g_h1 + (size_t)warp * DCOLS))[lane];
    uint4 u2 = ((const uint4*)(g_h2 + (size_t)warp * DCOLS))[lane];
    const __half2* h1 = (const __half2*)&u1;
    const __half2* h2 = (const __half2*)&u2;

    float r[8];
#pragma unroll
    for (int q = 0; q < 4; q++) {
        float2 f1 = __half22float2(h1[q]);
        float2 f2 = __half22float2(h2[q]);
        r[2 * q + 0] = f1.x + f2.x + a[2 * q + 0] * (1.f / 256.f);
        r[2 * q + 1] = f1.y + f2.y + a[2 * q + 1] * (1.f / 256.f);
    }
    float4 o0 = make_float4(s0.x + r[0] + b0.x, s0.y + r[1] + b0.y,
                            s0.z + r[2] + b0.z, s0.w + r[3] + b0.w);
    float4 o1 = make_float4(s1.x + r[4] + b1.x, s1.y + r[5] + b1.y,
                            s1.z + r[6] + b1.z, s1.w + r[7] + b1.w);
    *(float4*)(out + o) = o0;
    *(float4*)(out + o + 4) = o1;
}

// ======================= launch ============================================
extern "C" void kernel_launch(void* const* d_in, const int* in_sizes, int n_in,
                              void* d_out, int out_size)
{
    const float* x    = (const float*)d_in[0];
    const float* w    = (const float*)d_in[1];
    const float* bias = (const float*)d_in[2];
    const float* ew   = (const float*)d_in[3];
    const int*   er   = (const int*)d_in[4];
    const int*   ec   = (const int*)d_in[5];
    float* out = (float*)d_out;

    const int M = in_sizes[0] / DCOLS;
    const int E = in_sizes[3];
    const int NB = (M + 1023) / 1024;

    // 1) fp16 tensor-core GEMM (double-buffered)
    dim3 ggrid(DCOLS / GBN, (M + GBM - 1) / GBM);
    gemm_f16_kernel<<<ggrid, 256>>>(x, w, M);

    // 2) CSR build (parallel scan, interleaved col+w)
    zero_counts_kernel<<<(M + 255) / 256, 256>>>(M);
    count_kernel<<<2048, 256>>>(er, E);
    local_scan_kernel<<<NB, 1024>>>(M);
    scan_sums_kernel<<<1, 128>>>(NB);
    add_off_kernel<<<NB, 1024>>>(M, E);
    scatter_kernel<<<2048, 256>>>(er, ec, ew, E);

    // 3) hops: fp16 gather, fp8 gather, fp8 gather + fused combine
    const int sblocks = (int)(((size_t)M * 32 + 255) / 256);
    spmm1_kernel<<<sblocks, 256>>>(M);
    spmm2_kernel<<<sblocks, 256>>>(M);
    spmm3_combine_kernel<<<sblocks, 256>>>(out, bias, M);
}

// round 6
// speedup vs baseline: 2.5390x; 1.0644x over previous
#include <cuda_runtime.h>
#include <cuda_fp16.h>
#include <cstdint>

#define NROWS 100000
#define DCOLS 256
#define NEDGE 3200000

// ---------------- scratch (device globals: allocation-free) ----------------
__device__ float   g_sup32[(size_t)NROWS * DCOLS];  // support fp32 (for output)
__device__ __half  g_s16 [(size_t)NROWS * DCOLS];   // support fp16 (hop1 gather)
__device__ __half  g_h1  [(size_t)NROWS * DCOLS];   // A s   fp16 (output term)
__device__ __half  g_h2  [(size_t)NROWS * DCOLS];   // A^2 s fp16 (output term)
__device__ unsigned char g_h1q[(size_t)NROWS * DCOLS]; // h1 * 16  (e4m3, hop2 gather)
__device__ unsigned char g_h2q[(size_t)NROWS * DCOLS]; // h2 * 256 (e4m3, hop3 gather)
__device__ int     g_counts[NROWS];
__device__ int     g_row_start[NROWS + 1];
__device__ int     g_cursor[NROWS];
__device__ int2    g_csr[NEDGE];          // (col, weight bits) interleaved
__device__ int     g_blocksums[128];
__device__ int     g_blockoff[128];

// ======================= fp16 tensor-core GEMM =============================
#define GBM 128
#define GBN 128
#define GBK 32
#define HST 40   // padded smem stride (halves)

__global__ __launch_bounds__(256) void gemm_f16_kernel(
    const float* __restrict__ x, const float* __restrict__ w, int M)
{
    __shared__ __half As[GBM][HST];
    __shared__ __half Bs[GBN][HST];   // transposed: Bs[n][k]

    const int tid  = threadIdx.x;
    const int lane = tid & 31;
    const int warp = tid >> 5;
    const int gid  = lane >> 2;
    const int tig  = lane & 3;

    const int row0 = blockIdx.y * GBM;
    const int col0 = blockIdx.x * GBN;
    const int warp_m = (warp >> 2) * 64;
    const int warp_n = (warp & 3) * 32;

    int a_r[4], a_k[4], b_k[4], b_n[4];
#pragma unroll
    for (int h = 0; h < 4; h++) {
        const int idx = tid + h * 256;
        a_r[h] = idx >> 3;
        a_k[h] = (idx & 7) * 4;
        b_k[h] = idx >> 5;
        b_n[h] = (idx & 31) * 4;
    }

    float acc[4][4][4];
#pragma unroll
    for (int i = 0; i < 4; i++)
#pragma unroll
        for (int j = 0; j < 4; j++)
#pragma unroll
            for (int q = 0; q < 4; q++) acc[i][j][q] = 0.f;

    float4 ap[4], bp[4];
#pragma unroll
    for (int h = 0; h < 4; h++) {
        const int grow = row0 + a_r[h];
        ap[h] = make_float4(0.f, 0.f, 0.f, 0.f);
        if (grow < M)
            ap[h] = *(const float4*)(x + (size_t)grow * DCOLS + a_k[h]);
        bp[h] = *(const float4*)(w + (size_t)b_k[h] * DCOLS + col0 + b_n[h]);
    }

    for (int k0 = 0; k0 < DCOLS; k0 += GBK) {
#pragma unroll
        for (int h = 0; h < 4; h++) {
            *(__half2*)&As[a_r[h]][a_k[h]]     = __floats2half2_rn(ap[h].x, ap[h].y);
            *(__half2*)&As[a_r[h]][a_k[h] + 2] = __floats2half2_rn(ap[h].z, ap[h].w);
            Bs[b_n[h] + 0][b_k[h]] = __float2half_rn(bp[h].x);
            Bs[b_n[h] + 1][b_k[h]] = __float2half_rn(bp[h].y);
            Bs[b_n[h] + 2][b_k[h]] = __float2half_rn(bp[h].z);
            Bs[b_n[h] + 3][b_k[h]] = __float2half_rn(bp[h].w);
        }
        __syncthreads();

        const int kn = k0 + GBK;
        if (kn < DCOLS) {
#pragma unroll
            for (int h = 0; h < 4; h++) {
                const int grow = row0 + a_r[h];
                ap[h] = make_float4(0.f, 0.f, 0.f, 0.f);
                if (grow < M)
                    ap[h] = *(const float4*)(x + (size_t)grow * DCOLS + kn + a_k[h]);
                bp[h] = *(const float4*)(w + (size_t)(kn + b_k[h]) * DCOLS + col0 + b_n[h]);
            }
        }

#pragma unroll
        for (int ks = 0; ks < 2; ks++) {
            const int kk = ks * 16;
            unsigned a[4][4], b[4][2];
#pragma unroll
            for (int i = 0; i < 4; i++) {
                const int rm = warp_m + i * 16;
                a[i][0] = *(const unsigned*)&As[rm + gid    ][kk + 2 * tig];
                a[i][1] = *(const unsigned*)&As[rm + gid + 8][kk + 2 * tig];
                a[i][2] = *(const unsigned*)&As[rm + gid    ][kk + 8 + 2 * tig];
                a[i][3] = *(const unsigned*)&As[rm + gid + 8][kk + 8 + 2 * tig];
            }
#pragma unroll
            for (int j = 0; j < 4; j++) {
                const int n = warp_n + j * 8 + gid;
                b[j][0] = *(const unsigned*)&Bs[n][kk + 2 * tig];
                b[j][1] = *(const unsigned*)&Bs[n][kk + 8 + 2 * tig];
            }
#pragma unroll
            for (int i = 0; i < 4; i++)
#pragma unroll
                for (int j = 0; j < 4; j++) {
                    asm volatile(
                        "mma.sync.aligned.m16n8k16.row.col.f32.f16.f16.f32 "
                        "{%0,%1,%2,%3}, {%4,%5,%6,%7}, {%8,%9}, {%0,%1,%2,%3};"
                        : "+f"(acc[i][j][0]), "+f"(acc[i][j][1]),
                          "+f"(acc[i][j][2]), "+f"(acc[i][j][3])
                        : "r"(a[i][0]), "r"(a[i][1]), "r"(a[i][2]), "r"(a[i][3]),
                          "r"(b[j][0]), "r"(b[j][1]));
                }
        }
        __syncthreads();
    }

#pragma unroll
    for (int i = 0; i < 4; i++) {
#pragma unroll
        for (int h = 0; h < 2; h++) {
            const int r = row0 + warp_m + i * 16 + gid + h * 8;
            if (r < M) {
#pragma unroll
                for (int j = 0; j < 4; j++) {
                    const int c = col0 + warp_n + j * 8 + 2 * tig;
                    const float v0 = acc[i][j][2 * h];
                    const float v1 = acc[i][j][2 * h + 1];
                    *(float2*)(g_sup32 + (size_t)r * DCOLS + c) = make_float2(v0, v1);
                    *(__half2*)(g_s16 + (size_t)r * DCOLS + c) = __floats2half2_rn(v0, v1);
                }
            }
        }
    }
}

// ======================= CSR build =========================================
__global__ void zero_counts_kernel(int M)
{
    for (int i = blockIdx.x * blockDim.x + threadIdx.x; i < M;
         i += gridDim.x * blockDim.x)
        g_counts[i] = 0;
}

__global__ void count_kernel(const int* __restrict__ erow, int E)
{
    for (int i = blockIdx.x * blockDim.x + threadIdx.x; i < E;
         i += gridDim.x * blockDim.x)
        atomicAdd(&g_counts[erow[i]], 1);
}

__global__ __launch_bounds__(1024) void local_scan_kernel(int M)
{
    __shared__ int sh[1024];
    const int t = threadIdx.x;
    const int i = blockIdx.x * 1024 + t;
    const int v = (i < M) ? g_counts[i] : 0;
    sh[t] = v;
    __syncthreads();
#pragma unroll
    for (int d = 1; d < 1024; d <<= 1) {
        int u = (t >= d) ? sh[t - d] : 0;
        __syncthreads();
        sh[t] += u;
        __syncthreads();
    }
    if (i < M) g_row_start[i] = sh[t] - v;
    if (t == 1023) g_blocksums[blockIdx.x] = sh[1023];
}

__global__ __launch_bounds__(128) void scan_sums_kernel(int NB)
{
    __shared__ int sh[128];
    const int t = threadIdx.x;
    const int v = (t < NB) ? g_blocksums[t] : 0;
    sh[t] = v;
    __syncthreads();
#pragma unroll
    for (int d = 1; d < 128; d <<= 1) {
        int u = (t >= d) ? sh[t - d] : 0;
        __syncthreads();
        sh[t] += u;
        __syncthreads();
    }
    g_blockoff[t] = sh[t] - v;
}

__global__ __launch_bounds__(1024) void add_off_kernel(int M, int E)
{
    const int t = threadIdx.x;
    const int i = blockIdx.x * 1024 + t;
    if (i < M) {
        const int rs = g_row_start[i] + g_blockoff[blockIdx.x];
        g_row_start[i] = rs;
        g_cursor[i] = rs;
    }
    if (blockIdx.x == 0 && t == 0) g_row_start[M] = E;
}

__global__ void scatter_kernel(const int* __restrict__ erow,
                               const int* __restrict__ ecol,
                               const float* __restrict__ ew, int E)
{
    for (int i = blockIdx.x * blockDim.x + threadIdx.x; i < E;
         i += gridDim.x * blockDim.x) {
        const int r = erow[i];
        const int pos = atomicAdd(&g_cursor[r], 1);
        g_csr[pos] = make_int2(ecol[i], __float_as_int(ew[i]));
    }
}

// ======================= fp8 / half helpers ================================
__device__ __forceinline__ __half2 fp8x2_to_h2(unsigned short v)
{
    unsigned r;
    asm("cvt.rn.f16x2.e4m3x2 %0, %1;" : "=r"(r) : "h"(v));
    return *(__half2*)&r;
}

__device__ __forceinline__ unsigned short h2_to_fp8x2(__half2 h)
{
    unsigned short r;
    unsigned u = *(unsigned*)&h;
    asm("cvt.rn.satfinite.e4m3x2.f16x2 %0, %1;" : "=h"(r) : "r"(u));
    return r;
}

__device__ __forceinline__ unsigned short f2_to_fp8x2(float lo, float hi)
{
    unsigned short r;
    asm("cvt.rn.satfinite.e4m3x2.f32 %0, %1, %2;" : "=h"(r) : "f"(hi), "f"(lo));
    return r;
}

__device__ __forceinline__ unsigned packh2(float x, float y)
{
    __half2 h = __floats2half2_rn(x, y);
    return *(unsigned*)&h;
}

// fp32 accumulate of one fp16 row chunk
__device__ __forceinline__ void acc_h16(float* a, float wgt, uint4 v)
{
    const __half2* h = (const __half2*)&v;
#pragma unroll
    for (int q = 0; q < 4; q++) {
        float2 f = __half22float2(h[q]);
        a[2 * q + 0] = fmaf(wgt, f.x, a[2 * q + 0]);
        a[2 * q + 1] = fmaf(wgt, f.y, a[2 * q + 1]);
    }
}

// half2 accumulate of one fp8 row chunk (cheap: 4 cvt + 4 HFMA2)
__device__ __forceinline__ void acc_q8h(__half2* a, __half2 w2, uint2 v)
{
    const unsigned short* p = (const unsigned short*)&v;
#pragma unroll
    for (int q = 0; q < 4; q++)
        a[q] = __hfma2(w2, fp8x2_to_h2(p[q]), a[q]);
}

// ======================= SpMM hops =========================================
// hop1: h1 = A * s16 (fp16 gather, fp32 accum); writes h1 fp16 + h1q fp8(x16)
__global__ __launch_bounds__(256) void spmm1_kernel(int M)
{
    const int warp = (blockIdx.x * blockDim.x + threadIdx.x) >> 5;
    if (warp >= M) return;
    const int lane = threadIdx.x & 31;
    const int s = g_row_start[warp];
    const int e = g_row_start[warp + 1];

    float a[8];
#pragma unroll
    for (int q = 0; q < 8; q++) a[q] = 0.f;

    int j = s;
    if ((j & 1) && j < e) {                      // align to 16B for int4 loads
        int2 c = g_csr[j];
        uint4 v = ((const uint4*)(g_s16 + (size_t)c.x * DCOLS))[lane];
        acc_h16(a, __int_as_float(c.y), v);
        j++;
    }
    for (; j + 7 < e; j += 8) {
        int4 p0 = *(const int4*)&g_csr[j];
        int4 p1 = *(const int4*)&g_csr[j + 2];
        int4 p2 = *(const int4*)&g_csr[j + 4];
        int4 p3 = *(const int4*)&g_csr[j + 6];
        uint4 v0 = ((const uint4*)(g_s16 + (size_t)p0.x * DCOLS))[lane];
        uint4 v1 = ((const uint4*)(g_s16 + (size_t)p0.z * DCOLS))[lane];
        uint4 v2 = ((const uint4*)(g_s16 + (size_t)p1.x * DCOLS))[lane];
        uint4 v3 = ((const uint4*)(g_s16 + (size_t)p1.z * DCOLS))[lane];
        uint4 v4 = ((const uint4*)(g_s16 + (size_t)p2.x * DCOLS))[lane];
        uint4 v5 = ((const uint4*)(g_s16 + (size_t)p2.z * DCOLS))[lane];
        uint4 v6 = ((const uint4*)(g_s16 + (size_t)p3.x * DCOLS))[lane];
        uint4 v7 = ((const uint4*)(g_s16 + (size_t)p3.z * DCOLS))[lane];
        acc_h16(a, __int_as_float(p0.y), v0);
        acc_h16(a, __int_as_float(p0.w), v1);
        acc_h16(a, __int_as_float(p1.y), v2);
        acc_h16(a, __int_as_float(p1.w), v3);
        acc_h16(a, __int_as_float(p2.y), v4);
        acc_h16(a, __int_as_float(p2.w), v5);
        acc_h16(a, __int_as_float(p3.y), v6);
        acc_h16(a, __int_as_float(p3.w), v7);
    }
    for (; j < e; j++) {
        int2 c = g_csr[j];
        uint4 v = ((const uint4*)(g_s16 + (size_t)c.x * DCOLS))[lane];
        acc_h16(a, __int_as_float(c.y), v);
    }

    uint4 o;
    o.x = packh2(a[0], a[1]); o.y = packh2(a[2], a[3]);
    o.z = packh2(a[4], a[5]); o.w = packh2(a[6], a[7]);
    ((uint4*)(g_h1 + (size_t)warp * DCOLS))[lane] = o;

    ushort4 q8;
    q8.x = f2_to_fp8x2(a[0] * 16.f, a[1] * 16.f);
    q8.y = f2_to_fp8x2(a[2] * 16.f, a[3] * 16.f);
    q8.z = f2_to_fp8x2(a[4] * 16.f, a[5] * 16.f);
    q8.w = f2_to_fp8x2(a[6] * 16.f, a[7] * 16.f);
    ((ushort4*)(g_h1q + (size_t)warp * DCOLS))[lane] = q8;
}

// hop2: gathers h1q (fp8 = h1*16), half2 accum (a = 16*h2);
// writes h2 fp16 + h2q fp8(=h2*256 = a*16)
__global__ __launch_bounds__(256) void spmm2_kernel(int M)
{
    const int warp = (blockIdx.x * blockDim.x + threadIdx.x) >> 5;
    if (warp >= M) return;
    const int lane = threadIdx.x & 31;
    const int s = g_row_start[warp];
    const int e = g_row_start[warp + 1];

    __half2 a[4];
#pragma unroll
    for (int q = 0; q < 4; q++) a[q] = __half2half2(__float2half(0.f));

    int j = s;
    if ((j & 1) && j < e) {
        int2 c = g_csr[j];
        __half2 w2 = __half2half2(__float2half_rn(__int_as_float(c.y)));
        acc_q8h(a, w2, ((const uint2*)(g_h1q + (size_t)c.x * DCOLS))[lane]);
        j++;
    }
    for (; j + 7 < e; j += 8) {
        int4 p0 = *(const int4*)&g_csr[j];
        int4 p1 = *(const int4*)&g_csr[j + 2];
        int4 p2 = *(const int4*)&g_csr[j + 4];
        int4 p3 = *(const int4*)&g_csr[j + 6];
        uint2 v0 = ((const uint2*)(g_h1q + (size_t)p0.x * DCOLS))[lane];
        uint2 v1 = ((const uint2*)(g_h1q + (size_t)p0.z * DCOLS))[lane];
        uint2 v2 = ((const uint2*)(g_h1q + (size_t)p1.x * DCOLS))[lane];
        uint2 v3 = ((const uint2*)(g_h1q + (size_t)p1.z * DCOLS))[lane];
        uint2 v4 = ((const uint2*)(g_h1q + (size_t)p2.x * DCOLS))[lane];
        uint2 v5 = ((const uint2*)(g_h1q + (size_t)p2.z * DCOLS))[lane];
        uint2 v6 = ((const uint2*)(g_h1q + (size_t)p3.x * DCOLS))[lane];
        uint2 v7 = ((const uint2*)(g_h1q + (size_t)p3.z * DCOLS))[lane];
        acc_q8h(a, __half2half2(__float2half_rn(__int_as_float(p0.y))), v0);
        acc_q8h(a, __half2half2(__float2half_rn(__int_as_float(p0.w))), v1);
        acc_q8h(a, __half2half2(__float2half_rn(__int_as_float(p1.y))), v2);
        acc_q8h(a, __half2half2(__float2half_rn(__int_as_float(p1.w))), v3);
        acc_q8h(a, __half2half2(__float2half_rn(__int_as_float(p2.y))), v4);
        acc_q8h(a, __half2half2(__float2half_rn(__int_as_float(p2.w))), v5);
        acc_q8h(a, __half2half2(__float2half_rn(__int_as_float(p3.y))), v6);
        acc_q8h(a, __half2half2(__float2half_rn(__int_as_float(p3.w))), v7);
    }
    for (; j < e; j++) {
        int2 c = g_csr[j];
        __half2 w2 = __half2half2(__float2half_rn(__int_as_float(c.y)));
        acc_q8h(a, w2, ((const uint2*)(g_h1q + (size_t)c.x * DCOLS))[lane]);
    }

    // h2 = a/16 (fp16); h2q = a*16 (fp8)
    const __half2 inv16 = __half2half2(__float2half(0.0625f));
    const __half2 x16   = __half2half2(__float2half(16.f));
    uint4 o;
    __half2 h0 = __hmul2(a[0], inv16), h1v = __hmul2(a[1], inv16);
    __half2 h2v = __hmul2(a[2], inv16), h3v = __hmul2(a[3], inv16);
    o.x = *(unsigned*)&h0; o.y = *(unsigned*)&h1v;
    o.z = *(unsigned*)&h2v; o.w = *(unsigned*)&h3v;
    ((uint4*)(g_h2 + (size_t)warp * DCOLS))[lane] = o;

    ushort4 q8;
    q8.x = h2_to_fp8x2(__hmul2(a[0], x16));
    q8.y = h2_to_fp8x2(__hmul2(a[1], x16));
    q8.z = h2_to_fp8x2(__hmul2(a[2], x16));
    q8.w = h2_to_fp8x2(__hmul2(a[3], x16));
    ((ushort4*)(g_h2q + (size_t)warp * DCOLS))[lane] = q8;
}

// hop3 fused with combine: out = sup32 + h1 + h2 + (A*h2q)/256 + bias
__global__ __launch_bounds__(256) void spmm3_combine_kernel(
    float* __restrict__ out, const float* __restrict__ bias, int M)
{
    const int warp = (blockIdx.x * blockDim.x + threadIdx.x) >> 5;
    if (warp >= M) return;
    const int lane = threadIdx.x & 31;
    const int s = g_row_start[warp];
    const int e = g_row_start[warp + 1];

    __half2 a[4];
#pragma unroll
    for (int q = 0; q < 4; q++) a[q] = __half2half2(__float2half(0.f));

    int j = s;
    if ((j & 1) && j < e) {
        int2 c = g_csr[j];
        __half2 w2 = __half2half2(__float2half_rn(__int_as_float(c.y)));
        acc_q8h(a, w2, ((const uint2*)(g_h2q + (size_t)c.x * DCOLS))[lane]);
        j++;
    }
    for (; j + 7 < e; j += 8) {
        int4 p0 = *(const int4*)&g_csr[j];
        int4 p1 = *(const int4*)&g_csr[j + 2];
        int4 p2 = *(const int4*)&g_csr[j + 4];
        int4 p3 = *(const int4*)&g_csr[j + 6];
        uint2 v0 = ((const uint2*)(g_h2q + (size_t)p0.x * DCOLS))[lane];
        uint2 v1 = ((const uint2*)(g_h2q + (size_t)p0.z * DCOLS))[lane];
        uint2 v2 = ((const uint2*)(g_h2q + (size_t)p1.x * DCOLS))[lane];
        uint2 v3 = ((const uint2*)(g_h2q + (size_t)p1.z * DCOLS))[lane];
        uint2 v4 = ((const uint2*)(g_h2q + (size_t)p2.x * DCOLS))[lane];
        uint2 v5 = ((const uint2*)(g_h2q + (size_t)p2.z * DCOLS))[lane];
        uint2 v6 = ((const uint2*)(g_h2q + (size_t)p3.x * DCOLS))[lane];
        uint2 v7 = ((const uint2*)(g_h2q + (size_t)p3.z * DCOLS))[lane];
        acc_q8h(a, __half2half2(__float2half_rn(__int_as_float(p0.y))), v0);
        acc_q8h(a, __half2half2(__float2half_rn(__int_as_float(p0.w))), v1);
        acc_q8h(a, __half2half2(__float2half_rn(__int_as_float(p1.y))), v2);
        acc_q8h(a, __half2half2(__float2half_rn(__int_as_float(p1.w))), v3);
        acc_q8h(a, __half2half2(__float2half_rn(__int_as_float(p2.y))), v4);
        acc_q8h(a, __half2half2(__float2half_rn(__int_as_float(p2.w))), v5);
        acc_q8h(a, __half2half2(__float2half_rn(__int_as_float(p3.y))), v6);
        acc_q8h(a, __half2half2(__float2half_rn(__int_as_float(p3.w))), v7);
    }
    for (; j < e; j++) {
        int2 c = g_csr[j];
        __half2 w2 = __half2half2(__float2half_rn(__int_as_float(c.y)));
        acc_q8h(a, w2, ((const uint2*)(g_h2q + (size_t)c.x * DCOLS))[lane]);
    }

    const size_t o = (size_t)warp * DCOLS + lane * 8;
    float4 s0 = *(const float4*)(g_sup32 + o);
    float4 s1 = *(const float4*)(g_sup32 + o + 4);
    float4 b0 = *(const float4*)(bias + lane * 8);
    float4 b1 = *(const float4*)(bias + lane * 8 + 4);
    uint4 u1 = ((const uint4*)(g_h1 + (size_t)warp * DCOLS))[lane];
    uint4 u2 = ((const uint4*)(g_h2 + (size_t)warp * DCOLS))[lane];
    const __half2* h1 = (const __half2*)&u1;
    const __half2* h2 = (const __half2*)&u2;

    float r[8];
#pragma unroll
    for (int q = 0; q < 4; q++) {
        float2 f1 = __half22float2(h1[q]);
        float2 f2 = __half22float2(h2[q]);
        float2 f3 = __half22float2(a[q]);          // = 256 * h3
        r[2 * q + 0] = f1.x + f2.x + f3.x * (1.f / 256.f);
        r[2 * q + 1] = f1.y + f2.y + f3.y * (1.f / 256.f);
    }
    float4 o0 = make_float4(s0.x + r[0] + b0.x, s0.y + r[1] + b0.y,
                            s0.z + r[2] + b0.z, s0.w + r[3] + b0.w);
    float4 o1 = make_float4(s1.x + r[4] + b1.x, s1.y + r[5] + b1.y,
                            s1.z + r[6] + b1.z, s1.w + r[7] + b1.w);
    *(float4*)(out + o) = o0;
    *(float4*)(out + o + 4) = o1;
}

// ======================= launch ============================================
extern "C" void kernel_launch(void* const* d_in, const int* in_sizes, int n_in,
                              void* d_out, int out_size)
{
    const float* x    = (const float*)d_in[0];
    const float* w    = (const float*)d_in[1];
    const float* bias = (const float*)d_in[2];
    const float* ew   = (const float*)d_in[3];
    const int*   er   = (const int*)d_in[4];
    const int*   ec   = (const int*)d_in[5];
    float* out = (float*)d_out;

    const int M = in_sizes[0] / DCOLS;
    const int E = in_sizes[3];
    const int NB = (M + 1023) / 1024;

    // 1) fp16 tensor-core GEMM (double-buffered)
    dim3 ggrid(DCOLS / GBN, (M + GBM - 1) / GBM);
    gemm_f16_kernel<<<ggrid, 256>>>(x, w, M);

    // 2) CSR build (parallel scan, interleaved col+w)
    zero_counts_kernel<<<(M + 255) / 256, 256>>>(M);
    count_kernel<<<2048, 256>>>(er, E);
    local_scan_kernel<<<NB, 1024>>>(M);
    scan_sums_kernel<<<1, 128>>>(NB);
    add_off_kernel<<<NB, 1024>>>(M, E);
    scatter_kernel<<<2048, 256>>>(er, ec, ew, E);

    // 3) hops: fp16 gather (fp32 acc), fp8 gather (half2 acc) x2, fused combine
    const int sblocks = (int)(((size_t)M * 32 + 255) / 256);
    spmm1_kernel<<<sblocks, 256>>>(M);
    spmm2_kernel<<<sblocks, 256>>>(M);
    spmm3_combine_kernel<<<sblocks, 256>>>(out, bias, M);
}

// round 7
// speedup vs baseline: 2.5846x; 1.0180x over previous
#include <cuda_runtime.h>
#include <cuda_fp16.h>
#include <cstdint>

#define NROWS 100000
#define DCOLS 256
#define NEDGE 3200000

// ---------------- scratch (device globals: allocation-free) ----------------
__device__ float   g_sup32[(size_t)NROWS * DCOLS];  // support fp32 (for output)
__device__ __half  g_s16 [(size_t)NROWS * DCOLS];   // support fp16 (hop1 gather)
__device__ __half  g_h1  [(size_t)NROWS * DCOLS];   // A s   fp16 (output term)
__device__ __half  g_h2  [(size_t)NROWS * DCOLS];   // A^2 s fp16 (output term)
__device__ unsigned char g_h1q[(size_t)NROWS * DCOLS]; // h1 * 16  (e4m3, hop2 gather)
__device__ unsigned char g_h2q[(size_t)NROWS * DCOLS]; // h2 * 256 (e4m3, hop3 gather)
__device__ int     g_counts[NROWS];
__device__ int     g_row_start[NROWS + 1];
__device__ int     g_cursor[NROWS];
__device__ int2    g_csr[NEDGE];          // (col, weight bits) interleaved
__device__ int     g_blocksums[128];
__device__ int     g_blockoff[128];

// ======================= fp16 tensor-core GEMM =============================
#define GBM 128
#define GBN 128
#define GBK 32
#define HST 40   // padded smem stride (halves)

__global__ __launch_bounds__(256) void gemm_f16_kernel(
    const float* __restrict__ x, const float* __restrict__ w, int M)
{
    __shared__ __half As[GBM][HST];
    __shared__ __half Bs[GBN][HST];   // transposed: Bs[n][k]

    const int tid  = threadIdx.x;
    const int lane = tid & 31;
    const int warp = tid >> 5;
    const int gid  = lane >> 2;
    const int tig  = lane & 3;

    const int row0 = blockIdx.y * GBM;
    const int col0 = blockIdx.x * GBN;
    const int warp_m = (warp >> 2) * 64;
    const int warp_n = (warp & 3) * 32;

    int a_r[4], a_k[4], b_k[4], b_n[4];
#pragma unroll
    for (int h = 0; h < 4; h++) {
        const int idx = tid + h * 256;
        a_r[h] = idx >> 3;
        a_k[h] = (idx & 7) * 4;
        b_k[h] = idx >> 5;
        b_n[h] = (idx & 31) * 4;
    }

    float acc[4][4][4];
#pragma unroll
    for (int i = 0; i < 4; i++)
#pragma unroll
        for (int j = 0; j < 4; j++)
#pragma unroll
            for (int q = 0; q < 4; q++) acc[i][j][q] = 0.f;

    float4 ap[4], bp[4];
#pragma unroll
    for (int h = 0; h < 4; h++) {
        const int grow = row0 + a_r[h];
        ap[h] = make_float4(0.f, 0.f, 0.f, 0.f);
        if (grow < M)
            ap[h] = *(const float4*)(x + (size_t)grow * DCOLS + a_k[h]);
        bp[h] = *(const float4*)(w + (size_t)b_k[h] * DCOLS + col0 + b_n[h]);
    }

    for (int k0 = 0; k0 < DCOLS; k0 += GBK) {
#pragma unroll
        for (int h = 0; h < 4; h++) {
            *(__half2*)&As[a_r[h]][a_k[h]]     = __floats2half2_rn(ap[h].x, ap[h].y);
            *(__half2*)&As[a_r[h]][a_k[h] + 2] = __floats2half2_rn(ap[h].z, ap[h].w);
            Bs[b_n[h] + 0][b_k[h]] = __float2half_rn(bp[h].x);
            Bs[b_n[h] + 1][b_k[h]] = __float2half_rn(bp[h].y);
            Bs[b_n[h] + 2][b_k[h]] = __float2half_rn(bp[h].z);
            Bs[b_n[h] + 3][b_k[h]] = __float2half_rn(bp[h].w);
        }
        __syncthreads();

        const int kn = k0 + GBK;
        if (kn < DCOLS) {
#pragma unroll
            for (int h = 0; h < 4; h++) {
                const int grow = row0 + a_r[h];
                ap[h] = make_float4(0.f, 0.f, 0.f, 0.f);
                if (grow < M)
                    ap[h] = *(const float4*)(x + (size_t)grow * DCOLS + kn + a_k[h]);
                bp[h] = *(const float4*)(w + (size_t)(kn + b_k[h]) * DCOLS + col0 + b_n[h]);
            }
        }

#pragma unroll
        for (int ks = 0; ks < 2; ks++) {
            const int kk = ks * 16;
            unsigned a[4][4], b[4][2];
#pragma unroll
            for (int i = 0; i < 4; i++) {
                const int rm = warp_m + i * 16;
                a[i][0] = *(const unsigned*)&As[rm + gid    ][kk + 2 * tig];
                a[i][1] = *(const unsigned*)&As[rm + gid + 8][kk + 2 * tig];
                a[i][2] = *(const unsigned*)&As[rm + gid    ][kk + 8 + 2 * tig];
                a[i][3] = *(const unsigned*)&As[rm + gid + 8][kk + 8 + 2 * tig];
            }
#pragma unroll
            for (int j = 0; j < 4; j++) {
                const int n = warp_n + j * 8 + gid;
                b[j][0] = *(const unsigned*)&Bs[n][kk + 2 * tig];
                b[j][1] = *(const unsigned*)&Bs[n][kk + 8 + 2 * tig];
            }
#pragma unroll
            for (int i = 0; i < 4; i++)
#pragma unroll
                for (int j = 0; j < 4; j++) {
                    asm volatile(
                        "mma.sync.aligned.m16n8k16.row.col.f32.f16.f16.f32 "
                        "{%0,%1,%2,%3}, {%4,%5,%6,%7}, {%8,%9}, {%0,%1,%2,%3};"
                        : "+f"(acc[i][j][0]), "+f"(acc[i][j][1]),
                          "+f"(acc[i][j][2]), "+f"(acc[i][j][3])
                        : "r"(a[i][0]), "r"(a[i][1]), "r"(a[i][2]), "r"(a[i][3]),
                          "r"(b[j][0]), "r"(b[j][1]));
                }
        }
        __syncthreads();
    }

#pragma unroll
    for (int i = 0; i < 4; i++) {
#pragma unroll
        for (int h = 0; h < 2; h++) {
            const int r = row0 + warp_m + i * 16 + gid + h * 8;
            if (r < M) {
#pragma unroll
                for (int j = 0; j < 4; j++) {
                    const int c = col0 + warp_n + j * 8 + 2 * tig;
                    const float v0 = acc[i][j][2 * h];
                    const float v1 = acc[i][j][2 * h + 1];
                    *(float2*)(g_sup32 + (size_t)r * DCOLS + c) = make_float2(v0, v1);
                    *(__half2*)(g_s16 + (size_t)r * DCOLS + c) = __floats2half2_rn(v0, v1);
                }
            }
        }
    }
}

// ======================= CSR build =========================================
__global__ void zero_counts_kernel(int M)
{
    for (int i = blockIdx.x * blockDim.x + threadIdx.x; i < M;
         i += gridDim.x * blockDim.x)
        g_counts[i] = 0;
}

__global__ void count_kernel(const int* __restrict__ erow, int E)
{
    const int n4 = E >> 2;
    const int stride = gridDim.x * blockDim.x;
    const int t0 = blockIdx.x * blockDim.x + threadIdx.x;
    for (int i = t0; i < n4; i += stride) {
        int4 r = ((const int4*)erow)[i];
        atomicAdd(&g_counts[r.x], 1);
        atomicAdd(&g_counts[r.y], 1);
        atomicAdd(&g_counts[r.z], 1);
        atomicAdd(&g_counts[r.w], 1);
    }
    if (t0 < (E & 3))
        atomicAdd(&g_counts[erow[(n4 << 2) + t0]], 1);
}

__global__ __launch_bounds__(1024) void local_scan_kernel(int M)
{
    __shared__ int sh[1024];
    const int t = threadIdx.x;
    const int i = blockIdx.x * 1024 + t;
    const int v = (i < M) ? g_counts[i] : 0;
    sh[t] = v;
    __syncthreads();
#pragma unroll
    for (int d = 1; d < 1024; d <<= 1) {
        int u = (t >= d) ? sh[t - d] : 0;
        __syncthreads();
        sh[t] += u;
        __syncthreads();
    }
    if (i < M) g_row_start[i] = sh[t] - v;
    if (t == 1023) g_blocksums[blockIdx.x] = sh[1023];
}

__global__ __launch_bounds__(128) void scan_sums_kernel(int NB)
{
    __shared__ int sh[128];
    const int t = threadIdx.x;
    const int v = (t < NB) ? g_blocksums[t] : 0;
    sh[t] = v;
    __syncthreads();
#pragma unroll
    for (int d = 1; d < 128; d <<= 1) {
        int u = (t >= d) ? sh[t - d] : 0;
        __syncthreads();
        sh[t] += u;
        __syncthreads();
    }
    g_blockoff[t] = sh[t] - v;
}

__global__ __launch_bounds__(1024) void add_off_kernel(int M, int E)
{
    const int t = threadIdx.x;
    const int i = blockIdx.x * 1024 + t;
    if (i < M) {
        const int rs = g_row_start[i] + g_blockoff[blockIdx.x];
        g_row_start[i] = rs;
        g_cursor[i] = rs;
    }
    if (blockIdx.x == 0 && t == 0) g_row_start[M] = E;
}

__global__ void scatter_kernel(const int* __restrict__ erow,
                               const int* __restrict__ ecol,
                               const float* __restrict__ ew, int E)
{
    const int n4 = E >> 2;
    const int stride = gridDim.x * blockDim.x;
    const int t0 = blockIdx.x * blockDim.x + threadIdx.x;
    for (int i = t0; i < n4; i += stride) {
        int4   r4 = ((const int4*)erow)[i];
        int4   c4 = ((const int4*)ecol)[i];
        float4 w4 = ((const float4*)ew)[i];
        int p;
        p = atomicAdd(&g_cursor[r4.x], 1); g_csr[p] = make_int2(c4.x, __float_as_int(w4.x));
        p = atomicAdd(&g_cursor[r4.y], 1); g_csr[p] = make_int2(c4.y, __float_as_int(w4.y));
        p = atomicAdd(&g_cursor[r4.z], 1); g_csr[p] = make_int2(c4.z, __float_as_int(w4.z));
        p = atomicAdd(&g_cursor[r4.w], 1); g_csr[p] = make_int2(c4.w, __float_as_int(w4.w));
    }
    if (t0 < (E & 3)) {
        const int i = (n4 << 2) + t0;
        const int pos = atomicAdd(&g_cursor[erow[i]], 1);
        g_csr[pos] = make_int2(ecol[i], __float_as_int(ew[i]));
    }
}

// ======================= fp8 / half helpers ================================
__device__ __forceinline__ __half2 fp8x2_to_h2(unsigned short v)
{
    unsigned r;
    asm("cvt.rn.f16x2.e4m3x2 %0, %1;" : "=r"(r) : "h"(v));
    return *(__half2*)&r;
}

__device__ __forceinline__ unsigned short h2_to_fp8x2(__half2 h)
{
    unsigned short r;
    unsigned u = *(unsigned*)&h;
    asm("cvt.rn.satfinite.e4m3x2.f16x2 %0, %1;" : "=h"(r) : "r"(u));
    return r;
}

__device__ __forceinline__ unsigned short f2_to_fp8x2(float lo, float hi)
{
    unsigned short r;
    asm("cvt.rn.satfinite.e4m3x2.f32 %0, %1, %2;" : "=h"(r) : "f"(hi), "f"(lo));
    return r;
}

__device__ __forceinline__ unsigned packh2(float x, float y)
{
    __half2 h = __floats2half2_rn(x, y);
    return *(unsigned*)&h;
}

__device__ __forceinline__ void acc_h16(float* a, float wgt, uint4 v)
{
    const __half2* h = (const __half2*)&v;
#pragma unroll
    for (int q = 0; q < 4; q++) {
        float2 f = __half22float2(h[q]);
        a[2 * q + 0] = fmaf(wgt, f.x, a[2 * q + 0]);
        a[2 * q + 1] = fmaf(wgt, f.y, a[2 * q + 1]);
    }
}

__device__ __forceinline__ void acc_q8h(__half2* a, __half2 w2, uint2 v)
{
    const unsigned short* p = (const unsigned short*)&v;
#pragma unroll
    for (int q = 0; q < 4; q++)
        a[q] = __hfma2(w2, fp8x2_to_h2(p[q]), a[q]);
}

// ======================= SpMM hops =========================================
// hop1: h1 = A * s16 (fp16 gather, fp32 accum); writes h1 fp16 + h1q fp8(x16)
__global__ __launch_bounds__(256) void spmm1_kernel(int M)
{
    const int warp = (blockIdx.x * blockDim.x + threadIdx.x) >> 5;
    if (warp >= M) return;
    const int lane = threadIdx.x & 31;
    const int s = g_row_start[warp];
    const int e = g_row_start[warp + 1];

    float a[8];
#pragma unroll
    for (int q = 0; q < 8; q++) a[q] = 0.f;

    int j = s;
    if ((j & 1) && j < e) {
        int2 c = g_csr[j];
        uint4 v = ((const uint4*)(g_s16 + (size_t)c.x * DCOLS))[lane];
        acc_h16(a, __int_as_float(c.y), v);
        j++;
    }
    for (; j + 7 < e; j += 8) {
        int4 p0 = *(const int4*)&g_csr[j];
        int4 p1 = *(const int4*)&g_csr[j + 2];
        int4 p2 = *(const int4*)&g_csr[j + 4];
        int4 p3 = *(const int4*)&g_csr[j + 6];
        uint4 v0 = ((const uint4*)(g_s16 + (size_t)p0.x * DCOLS))[lane];
        uint4 v1 = ((const uint4*)(g_s16 + (size_t)p0.z * DCOLS))[lane];
        uint4 v2 = ((const uint4*)(g_s16 + (size_t)p1.x * DCOLS))[lane];
        uint4 v3 = ((const uint4*)(g_s16 + (size_t)p1.z * DCOLS))[lane];
        uint4 v4 = ((const uint4*)(g_s16 + (size_t)p2.x * DCOLS))[lane];
        uint4 v5 = ((const uint4*)(g_s16 + (size_t)p2.z * DCOLS))[lane];
        uint4 v6 = ((const uint4*)(g_s16 + (size_t)p3.x * DCOLS))[lane];
        uint4 v7 = ((const uint4*)(g_s16 + (size_t)p3.z * DCOLS))[lane];
        acc_h16(a, __int_as_float(p0.y), v0);
        acc_h16(a, __int_as_float(p0.w), v1);
        acc_h16(a, __int_as_float(p1.y), v2);
        acc_h16(a, __int_as_float(p1.w), v3);
        acc_h16(a, __int_as_float(p2.y), v4);
        acc_h16(a, __int_as_float(p2.w), v5);
        acc_h16(a, __int_as_float(p3.y), v6);
        acc_h16(a, __int_as_float(p3.w), v7);
    }
    for (; j < e; j++) {
        int2 c = g_csr[j];
        uint4 v = ((const uint4*)(g_s16 + (size_t)c.x * DCOLS))[lane];
        acc_h16(a, __int_as_float(c.y), v);
    }

    uint4 o;
    o.x = packh2(a[0], a[1]); o.y = packh2(a[2], a[3]);
    o.z = packh2(a[4], a[5]); o.w = packh2(a[6], a[7]);
    ((uint4*)(g_h1 + (size_t)warp * DCOLS))[lane] = o;

    ushort4 q8;
    q8.x = f2_to_fp8x2(a[0] * 16.f, a[1] * 16.f);
    q8.y = f2_to_fp8x2(a[2] * 16.f, a[3] * 16.f);
    q8.z = f2_to_fp8x2(a[4] * 16.f, a[5] * 16.f);
    q8.w = f2_to_fp8x2(a[6] * 16.f, a[7] * 16.f);
    ((ushort4*)(g_h1q + (size_t)warp * DCOLS))[lane] = q8;
}

// hop2: gathers h1q (fp8 = h1*16), half2 accum (a = 16*h2);
// writes h2 fp16 + h2q fp8(=h2*256 = a*16)
__global__ __launch_bounds__(256) void spmm2_kernel(int M)
{
    const int warp = (blockIdx.x * blockDim.x + threadIdx.x) >> 5;
    if (warp >= M) return;
    const int lane = threadIdx.x & 31;
    const int s = g_row_start[warp];
    const int e = g_row_start[warp + 1];

    __half2 a[4];
#pragma unroll
    for (int q = 0; q < 4; q++) a[q] = __half2half2(__float2half(0.f));

    int j = s;
    if ((j & 1) && j < e) {
        int2 c = g_csr[j];
        __half2 w2 = __half2half2(__float2half_rn(__int_as_float(c.y)));
        acc_q8h(a, w2, ((const uint2*)(g_h1q + (size_t)c.x * DCOLS))[lane]);
        j++;
    }
    for (; j + 7 < e; j += 8) {
        int4 p0 = *(const int4*)&g_csr[j];
        int4 p1 = *(const int4*)&g_csr[j + 2];
        int4 p2 = *(const int4*)&g_csr[j + 4];
        int4 p3 = *(const int4*)&g_csr[j + 6];
        uint2 v0 = ((const uint2*)(g_h1q + (size_t)p0.x * DCOLS))[lane];
        uint2 v1 = ((const uint2*)(g_h1q + (size_t)p0.z * DCOLS))[lane];
        uint2 v2 = ((const uint2*)(g_h1q + (size_t)p1.x * DCOLS))[lane];
        uint2 v3 = ((const uint2*)(g_h1q + (size_t)p1.z * DCOLS))[lane];
        uint2 v4 = ((const uint2*)(g_h1q + (size_t)p2.x * DCOLS))[lane];
        uint2 v5 = ((const uint2*)(g_h1q + (size_t)p2.z * DCOLS))[lane];
        uint2 v6 = ((const uint2*)(g_h1q + (size_t)p3.x * DCOLS))[lane];
        uint2 v7 = ((const uint2*)(g_h1q + (size_t)p3.z * DCOLS))[lane];
        acc_q8h(a, __half2half2(__float2half_rn(__int_as_float(p0.y))), v0);
        acc_q8h(a, __half2half2(__float2half_rn(__int_as_float(p0.w))), v1);
        acc_q8h(a, __half2half2(__float2half_rn(__int_as_float(p1.y))), v2);
        acc_q8h(a, __half2half2(__float2half_rn(__int_as_float(p1.w))), v3);
        acc_q8h(a, __half2half2(__float2half_rn(__int_as_float(p2.y))), v4);
        acc_q8h(a, __half2half2(__float2half_rn(__int_as_float(p2.w))), v5);
        acc_q8h(a, __half2half2(__float2half_rn(__int_as_float(p3.y))), v6);
        acc_q8h(a, __half2half2(__float2half_rn(__int_as_float(p3.w))), v7);
    }
    for (; j < e; j++) {
        int2 c = g_csr[j];
        __half2 w2 = __half2half2(__float2half_rn(__int_as_float(c.y)));
        acc_q8h(a, w2, ((const uint2*)(g_h1q + (size_t)c.x * DCOLS))[lane]);
    }

    const __half2 inv16 = __half2half2(__float2half(0.0625f));
    const __half2 x16   = __half2half2(__float2half(16.f));
    uint4 o;
    __half2 h0 = __hmul2(a[0], inv16), h1v = __hmul2(a[1], inv16);
    __half2 h2v = __hmul2(a[2], inv16), h3v = __hmul2(a[3], inv16);
    o.x = *(unsigned*)&h0; o.y = *(unsigned*)&h1v;
    o.z = *(unsigned*)&h2v; o.w = *(unsigned*)&h3v;
    ((uint4*)(g_h2 + (size_t)warp * DCOLS))[lane] = o;

    ushort4 q8;
    q8.x = h2_to_fp8x2(__hmul2(a[0], x16));
    q8.y = h2_to_fp8x2(__hmul2(a[1], x16));
    q8.z = h2_to_fp8x2(__hmul2(a[2], x16));
    q8.w = h2_to_fp8x2(__hmul2(a[3], x16));
    ((ushort4*)(g_h2q + (size_t)warp * DCOLS))[lane] = q8;
}

// hop3 fused with combine: out = sup32 + h1 + h2 + (A*h2q)/256 + bias
__global__ __launch_bounds__(256) void spmm3_combine_kernel(
    float* __restrict__ out, const float* __restrict__ bias, int M)
{
    const int warp = (blockIdx.x * blockDim.x + threadIdx.x) >> 5;
    if (warp >= M) return;
    const int lane = threadIdx.x & 31;
    const int s = g_row_start[warp];
    const int e = g_row_start[warp + 1];

    __half2 a[4];
#pragma unroll
    for (int q = 0; q < 4; q++) a[q] = __half2half2(__float2half(0.f));

    int j = s;
    if ((j & 1) && j < e) {
        int2 c = g_csr[j];
        __half2 w2 = __half2half2(__float2half_rn(__int_as_float(c.y)));
        acc_q8h(a, w2, ((const uint2*)(g_h2q + (size_t)c.x * DCOLS))[lane]);
        j++;
    }
    for (; j + 7 < e; j += 8) {
        int4 p0 = *(const int4*)&g_csr[j];
        int4 p1 = *(const int4*)&g_csr[j + 2];
        int4 p2 = *(const int4*)&g_csr[j + 4];
        int4 p3 = *(const int4*)&g_csr[j + 6];
        uint2 v0 = ((const uint2*)(g_h2q + (size_t)p0.x * DCOLS))[lane];
        uint2 v1 = ((const uint2*)(g_h2q + (size_t)p0.z * DCOLS))[lane];
        uint2 v2 = ((const uint2*)(g_h2q + (size_t)p1.x * DCOLS))[lane];
        uint2 v3 = ((const uint2*)(g_h2q + (size_t)p1.z * DCOLS))[lane];
        uint2 v4 = ((const uint2*)(g_h2q + (size_t)p2.x * DCOLS))[lane];
        uint2 v5 = ((const uint2*)(g_h2q + (size_t)p2.z * DCOLS))[lane];
        uint2 v6 = ((const uint2*)(g_h2q + (size_t)p3.x * DCOLS))[lane];
        uint2 v7 = ((const uint2*)(g_h2q + (size_t)p3.z * DCOLS))[lane];
        acc_q8h(a, __half2half2(__float2half_rn(__int_as_float(p0.y))), v0);
        acc_q8h(a, __half2half2(__float2half_rn(__int_as_float(p0.w))), v1);
        acc_q8h(a, __half2half2(__float2half_rn(__int_as_float(p1.y))), v2);
        acc_q8h(a, __half2half2(__float2half_rn(__int_as_float(p1.w))), v3);
        acc_q8h(a, __half2half2(__float2half_rn(__int_as_float(p2.y))), v4);
        acc_q8h(a, __half2half2(__float2half_rn(__int_as_float(p2.w))), v5);
        acc_q8h(a, __half2half2(__float2half_rn(__int_as_float(p3.y))), v6);
        acc_q8h(a, __half2half2(__float2half_rn(__int_as_float(p3.w))), v7);
    }
    for (; j < e; j++) {
        int2 c = g_csr[j];
        __half2 w2 = __half2half2(__float2half_rn(__int_as_float(c.y)));
        acc_q8h(a, w2, ((const uint2*)(g_h2q + (size_t)c.x * DCOLS))[lane]);
    }

    const size_t o = (size_t)warp * DCOLS + lane * 8;
    float4 s0 = *(const float4*)(g_sup32 + o);
    float4 s1 = *(const float4*)(g_sup32 + o + 4);
    float4 b0 = *(const float4*)(bias + lane * 8);
    float4 b1 = *(const float4*)(bias + lane * 8 + 4);
    uint4 u1 = ((const uint4*)(g_h1 + (size_t)warp * DCOLS))[lane];
    uint4 u2 = ((const uint4*)(g_h2 + (size_t)warp * DCOLS))[lane];
    const __half2* h1 = (const __half2*)&u1;
    const __half2* h2 = (const __half2*)&u2;

    float r[8];
#pragma unroll
    for (int q = 0; q < 4; q++) {
        float2 f1 = __half22float2(h1[q]);
        float2 f2 = __half22float2(h2[q]);
        float2 f3 = __half22float2(a[q]);          // = 256 * h3
        r[2 * q + 0] = f1.x + f2.x + f3.x * (1.f / 256.f);
        r[2 * q + 1] = f1.y + f2.y + f3.y * (1.f / 256.f);
    }
    float4 o0 = make_float4(s0.x + r[0] + b0.x, s0.y + r[1] + b0.y,
                            s0.z + r[2] + b0.z, s0.w + r[3] + b0.w);
    float4 o1 = make_float4(s1.x + r[4] + b1.x, s1.y + r[5] + b1.y,
                            s1.z + r[6] + b1.z, s1.w + r[7] + b1.w);
    *(float4*)(out + o) = o0;
    *(float4*)(out + o + 4) = o1;
}

// ======================= launch ============================================
extern "C" void kernel_launch(void* const* d_in, const int* in_sizes, int n_in,
                              void* d_out, int out_size)
{
    const float* x    = (const float*)d_in[0];
    const float* w    = (const float*)d_in[1];
    const float* bias = (const float*)d_in[2];
    const float* ew   = (const float*)d_in[3];
    const int*   er   = (const int*)d_in[4];
    const int*   ec   = (const int*)d_in[5];
    float* out = (float*)d_out;

    const int M = in_sizes[0] / DCOLS;
    const int E = in_sizes[3];
    const int NB = (M + 1023) / 1024;

    // Fork: CSR build on side stream, GEMM on main stream, join before hops.
    // (Host-side stream/event setup runs only during capture; the graph keeps
    //  only the dependency structure.)
    cudaStream_t s2;
    cudaEvent_t eFork, eJoin;
    cudaStreamCreateWithFlags(&s2, cudaStreamNonBlocking);
    cudaEventCreateWithFlags(&eFork, cudaEventDisableTiming);
    cudaEventCreateWithFlags(&eJoin, cudaEventDisableTiming);

    cudaEventRecord(eFork, 0);
    cudaStreamWaitEvent(s2, eFork, 0);

    // main stream: fp16 tensor-core GEMM
    dim3 ggrid(DCOLS / GBN, (M + GBM - 1) / GBM);
    gemm_f16_kernel<<<ggrid, 256>>>(x, w, M);

    // side stream: CSR build
    zero_counts_kernel<<<(M + 255) / 256, 256, 0, s2>>>(M);
    count_kernel<<<1024, 256, 0, s2>>>(er, E);
    local_scan_kernel<<<NB, 1024, 0, s2>>>(M);
    scan_sums_kernel<<<1, 128, 0, s2>>>(NB);
    add_off_kernel<<<NB, 1024, 0, s2>>>(M, E);
    scatter_kernel<<<1024, 256, 0, s2>>>(er, ec, ew, E);

    cudaEventRecord(eJoin, s2);
    cudaStreamWaitEvent(0, eJoin, 0);

    // hops (need both GEMM output and CSR)
    const int sblocks = (int)(((size_t)M * 32 + 255) / 256);
    spmm1_kernel<<<sblocks, 256>>>(M);
    spmm2_kernel<<<sblocks, 256>>>(M);
    spmm3_combine_kernel<<<sblocks, 256>>>(out, bias, M);

    cudaEventDestroy(eFork);
    cudaEventDestroy(eJoin);
    cudaStreamDestroy(s2);
}

// round 8
// speedup vs baseline: 2.7966x; 1.0820x over previous
#include <cuda_runtime.h>
#include <cuda_fp16.h>
#include <cstdint>

#define NROWS 100000
#define DCOLS 256
#define NEDGE 3200000

// ---------------- scratch (device globals: allocation-free) ----------------
__device__ __half  g_s16 [(size_t)NROWS * DCOLS];   // support fp16 (gather + output)
__device__ __half  g_h1  [(size_t)NROWS * DCOLS];   // A s   fp16 (output term)
__device__ __half  g_h2  [(size_t)NROWS * DCOLS];   // A^2 s fp16 (output term)
__device__ unsigned char g_h1q[(size_t)NROWS * DCOLS]; // h1 * 16  (e4m3, hop2 gather)
__device__ unsigned char g_h2q[(size_t)NROWS * DCOLS]; // h2 * 256 (e4m3, hop3 gather)
__device__ int     g_counts[NROWS];
__device__ int     g_row_start[NROWS + 1];
__device__ int     g_cursor[NROWS];
__device__ int2    g_csr[NEDGE];          // (col, weight bits) interleaved
__device__ int     g_blocksums[128];
__device__ int     g_blockoff[128];

// ======================= fp16 tensor-core GEMM =============================
#define GBM 128
#define GBN 128
#define GBK 32
#define HST 40   // padded smem stride (halves)

__global__ __launch_bounds__(256) void gemm_f16_kernel(
    const float* __restrict__ x, const float* __restrict__ w, int M)
{
    __shared__ __half As[GBM][HST];
    __shared__ __half Bs[GBN][HST];   // transposed: Bs[n][k]

    const int tid  = threadIdx.x;
    const int lane = tid & 31;
    const int warp = tid >> 5;
    const int gid  = lane >> 2;
    const int tig  = lane & 3;

    const int row0 = blockIdx.y * GBM;
    const int col0 = blockIdx.x * GBN;
    const int warp_m = (warp >> 2) * 64;
    const int warp_n = (warp & 3) * 32;

    int a_r[4], a_k[4], b_k[4], b_n[4];
#pragma unroll
    for (int h = 0; h < 4; h++) {
        const int idx = tid + h * 256;
        a_r[h] = idx >> 3;
        a_k[h] = (idx & 7) * 4;
        b_k[h] = idx >> 5;
        b_n[h] = (idx & 31) * 4;
    }

    float acc[4][4][4];
#pragma unroll
    for (int i = 0; i < 4; i++)
#pragma unroll
        for (int j = 0; j < 4; j++)
#pragma unroll
            for (int q = 0; q < 4; q++) acc[i][j][q] = 0.f;

    float4 ap[4], bp[4];
#pragma unroll
    for (int h = 0; h < 4; h++) {
        const int grow = row0 + a_r[h];
        ap[h] = make_float4(0.f, 0.f, 0.f, 0.f);
        if (grow < M)
            ap[h] = *(const float4*)(x + (size_t)grow * DCOLS + a_k[h]);
        bp[h] = *(const float4*)(w + (size_t)b_k[h] * DCOLS + col0 + b_n[h]);
    }

    for (int k0 = 0; k0 < DCOLS; k0 += GBK) {
#pragma unroll
        for (int h = 0; h < 4; h++) {
            *(__half2*)&As[a_r[h]][a_k[h]]     = __floats2half2_rn(ap[h].x, ap[h].y);
            *(__half2*)&As[a_r[h]][a_k[h] + 2] = __floats2half2_rn(ap[h].z, ap[h].w);
            Bs[b_n[h] + 0][b_k[h]] = __float2half_rn(bp[h].x);
            Bs[b_n[h] + 1][b_k[h]] = __float2half_rn(bp[h].y);
            Bs[b_n[h] + 2][b_k[h]] = __float2half_rn(bp[h].z);
            Bs[b_n[h] + 3][b_k[h]] = __float2half_rn(bp[h].w);
        }
        __syncthreads();

        const int kn = k0 + GBK;
        if (kn < DCOLS) {
#pragma unroll
            for (int h = 0; h < 4; h++) {
                const int grow = row0 + a_r[h];
                ap[h] = make_float4(0.f, 0.f, 0.f, 0.f);
                if (grow < M)
                    ap[h] = *(const float4*)(x + (size_t)grow * DCOLS + kn + a_k[h]);
                bp[h] = *(const float4*)(w + (size_t)(kn + b_k[h]) * DCOLS + col0 + b_n[h]);
            }
        }

#pragma unroll
        for (int ks = 0; ks < 2; ks++) {
            const int kk = ks * 16;
            unsigned a[4][4], b[4][2];
#pragma unroll
            for (int i = 0; i < 4; i++) {
                const int rm = warp_m + i * 16;
                a[i][0] = *(const unsigned*)&As[rm + gid    ][kk + 2 * tig];
                a[i][1] = *(const unsigned*)&As[rm + gid + 8][kk + 2 * tig];
                a[i][2] = *(const unsigned*)&As[rm + gid    ][kk + 8 + 2 * tig];
                a[i][3] = *(const unsigned*)&As[rm + gid + 8][kk + 8 + 2 * tig];
            }
#pragma unroll
            for (int j = 0; j < 4; j++) {
                const int n = warp_n + j * 8 + gid;
                b[j][0] = *(const unsigned*)&Bs[n][kk + 2 * tig];
                b[j][1] = *(const unsigned*)&Bs[n][kk + 8 + 2 * tig];
            }
#pragma unroll
            for (int i = 0; i < 4; i++)
#pragma unroll
                for (int j = 0; j < 4; j++) {
                    asm volatile(
                        "mma.sync.aligned.m16n8k16.row.col.f32.f16.f16.f32 "
                        "{%0,%1,%2,%3}, {%4,%5,%6,%7}, {%8,%9}, {%0,%1,%2,%3};"
                        : "+f"(acc[i][j][0]), "+f"(acc[i][j][1]),
                          "+f"(acc[i][j][2]), "+f"(acc[i][j][3])
                        : "r"(a[i][0]), "r"(a[i][1]), "r"(a[i][2]), "r"(a[i][3]),
                          "r"(b[j][0]), "r"(b[j][1]));
                }
        }
        __syncthreads();
    }

    // epilogue: write fp16 support only
#pragma unroll
    for (int i = 0; i < 4; i++) {
#pragma unroll
        for (int h = 0; h < 2; h++) {
            const int r = row0 + warp_m + i * 16 + gid + h * 8;
            if (r < M) {
#pragma unroll
                for (int j = 0; j < 4; j++) {
                    const int c = col0 + warp_n + j * 8 + 2 * tig;
                    *(__half2*)(g_s16 + (size_t)r * DCOLS + c) =
                        __floats2half2_rn(acc[i][j][2 * h], acc[i][j][2 * h + 1]);
                }
            }
        }
    }
}

// ======================= CSR build =========================================
__global__ void zero_counts_kernel(int M)
{
    for (int i = blockIdx.x * blockDim.x + threadIdx.x; i < M;
         i += gridDim.x * blockDim.x)
        g_counts[i] = 0;
}

__global__ void count_kernel(const int* __restrict__ erow, int E)
{
    const int n4 = E >> 2;
    const int stride = gridDim.x * blockDim.x;
    const int t0 = blockIdx.x * blockDim.x + threadIdx.x;
    for (int i = t0; i < n4; i += stride) {
        int4 r = ((const int4*)erow)[i];
        atomicAdd(&g_counts[r.x], 1);
        atomicAdd(&g_counts[r.y], 1);
        atomicAdd(&g_counts[r.z], 1);
        atomicAdd(&g_counts[r.w], 1);
    }
    if (t0 < (E & 3))
        atomicAdd(&g_counts[erow[(n4 << 2) + t0]], 1);
}

__global__ __launch_bounds__(1024) void local_scan_kernel(int M)
{
    __shared__ int sh[1024];
    const int t = threadIdx.x;
    const int i = blockIdx.x * 1024 + t;
    const int v = (i < M) ? g_counts[i] : 0;
    sh[t] = v;
    __syncthreads();
#pragma unroll
    for (int d = 1; d < 1024; d <<= 1) {
        int u = (t >= d) ? sh[t - d] : 0;
        __syncthreads();
        sh[t] += u;
        __syncthreads();
    }
    if (i < M) g_row_start[i] = sh[t] - v;
    if (t == 1023) g_blocksums[blockIdx.x] = sh[1023];
}

__global__ __launch_bounds__(128) void scan_sums_kernel(int NB)
{
    __shared__ int sh[128];
    const int t = threadIdx.x;
    const int v = (t < NB) ? g_blocksums[t] : 0;
    sh[t] = v;
    __syncthreads();
#pragma unroll
    for (int d = 1; d < 128; d <<= 1) {
        int u = (t >= d) ? sh[t - d] : 0;
        __syncthreads();
        sh[t] += u;
        __syncthreads();
    }
    g_blockoff[t] = sh[t] - v;
}

__global__ __launch_bounds__(1024) void add_off_kernel(int M, int E)
{
    const int t = threadIdx.x;
    const int i = blockIdx.x * 1024 + t;
    if (i < M) {
        const int rs = g_row_start[i] + g_blockoff[blockIdx.x];
        g_row_start[i] = rs;
        g_cursor[i] = rs;
    }
    if (blockIdx.x == 0 && t == 0) g_row_start[M] = E;
}

__global__ void scatter_kernel(const int* __restrict__ erow,
                               const int* __restrict__ ecol,
                               const float* __restrict__ ew, int E)
{
    const int n4 = E >> 2;
    const int stride = gridDim.x * blockDim.x;
    const int t0 = blockIdx.x * blockDim.x + threadIdx.x;
    for (int i = t0; i < n4; i += stride) {
        int4   r4 = ((const int4*)erow)[i];
        int4   c4 = ((const int4*)ecol)[i];
        float4 w4 = ((const float4*)ew)[i];
        int p;
        p = atomicAdd(&g_cursor[r4.x], 1); g_csr[p] = make_int2(c4.x, __float_as_int(w4.x));
        p = atomicAdd(&g_cursor[r4.y], 1); g_csr[p] = make_int2(c4.y, __float_as_int(w4.y));
        p = atomicAdd(&g_cursor[r4.z], 1); g_csr[p] = make_int2(c4.z, __float_as_int(w4.z));
        p = atomicAdd(&g_cursor[r4.w], 1); g_csr[p] = make_int2(c4.w, __float_as_int(w4.w));
    }
    if (t0 < (E & 3)) {
        const int i = (n4 << 2) + t0;
        const int pos = atomicAdd(&g_cursor[erow[i]], 1);
        g_csr[pos] = make_int2(ecol[i], __float_as_int(ew[i]));
    }
}

// ======================= fp8 / half helpers ================================
__device__ __forceinline__ __half2 fp8x2_to_h2(unsigned short v)
{
    unsigned r;
    asm("cvt.rn.f16x2.e4m3x2 %0, %1;" : "=r"(r) : "h"(v));
    return *(__half2*)&r;
}

__device__ __forceinline__ unsigned short h2_to_fp8x2(__half2 h)
{
    unsigned short r;
    unsigned u = *(unsigned*)&h;
    asm("cvt.rn.satfinite.e4m3x2.f16x2 %0, %1;" : "=h"(r) : "r"(u));
    return r;
}

// half2 accumulate of one fp16 row chunk (4 HFMA2)
__device__ __forceinline__ void acc_h16h(__half2* a, __half2 w2, uint4 v)
{
    const __half2* h = (const __half2*)&v;
#pragma unroll
    for (int q = 0; q < 4; q++)
        a[q] = __hfma2(w2, h[q], a[q]);
}

// half2 accumulate of one fp8 row chunk (4 cvt + 4 HFMA2)
__device__ __forceinline__ void acc_q8h(__half2* a, __half2 w2, uint2 v)
{
    const unsigned short* p = (const unsigned short*)&v;
#pragma unroll
    for (int q = 0; q < 4; q++)
        a[q] = __hfma2(w2, fp8x2_to_h2(p[q]), a[q]);
}

__device__ __forceinline__ __half2 wh2(int wbits)
{
    return __half2half2(__float2half_rn(__int_as_float(wbits)));
}

// ======================= SpMM hops =========================================
// hop1: h1 = A * s16 (fp16 gather, half2 accum, scaled x16 in-acc);
// writes h1 fp16 + h1q fp8(=h1*16)
__global__ __launch_bounds__(256) void spmm1_kernel(int M)
{
    const int warp = (blockIdx.x * blockDim.x + threadIdx.x) >> 5;
    if (warp >= M) return;
    const int lane = threadIdx.x & 31;
    const int s = g_row_start[warp];
    const int e = g_row_start[warp + 1];

    __half2 a[4];
#pragma unroll
    for (int q = 0; q < 4; q++) a[q] = __half2half2(__float2half(0.f));

    int j = s;
    if ((j & 1) && j < e) {
        int2 c = g_csr[j];
        // weight x16: keeps accumulator ~1.6, better fp16 resolution
        __half2 w2 = __half2half2(__float2half_rn(__int_as_float(c.y) * 16.f));
        acc_h16h(a, w2, ((const uint4*)(g_s16 + (size_t)c.x * DCOLS))[lane]);
        j++;
    }
    for (; j + 7 < e; j += 8) {
        int4 p0 = *(const int4*)&g_csr[j];
        int4 p1 = *(const int4*)&g_csr[j + 2];
        int4 p2 = *(const int4*)&g_csr[j + 4];
        int4 p3 = *(const int4*)&g_csr[j + 6];
        uint4 v0 = ((const uint4*)(g_s16 + (size_t)p0.x * DCOLS))[lane];
        uint4 v1 = ((const uint4*)(g_s16 + (size_t)p0.z * DCOLS))[lane];
        uint4 v2 = ((const uint4*)(g_s16 + (size_t)p1.x * DCOLS))[lane];
        uint4 v3 = ((const uint4*)(g_s16 + (size_t)p1.z * DCOLS))[lane];
        uint4 v4 = ((const uint4*)(g_s16 + (size_t)p2.x * DCOLS))[lane];
        uint4 v5 = ((const uint4*)(g_s16 + (size_t)p2.z * DCOLS))[lane];
        uint4 v6 = ((const uint4*)(g_s16 + (size_t)p3.x * DCOLS))[lane];
        uint4 v7 = ((const uint4*)(g_s16 + (size_t)p3.z * DCOLS))[lane];
        acc_h16h(a, __half2half2(__float2half_rn(__int_as_float(p0.y) * 16.f)), v0);
        acc_h16h(a, __half2half2(__float2half_rn(__int_as_float(p0.w) * 16.f)), v1);
        acc_h16h(a, __half2half2(__float2half_rn(__int_as_float(p1.y) * 16.f)), v2);
        acc_h16h(a, __half2half2(__float2half_rn(__int_as_float(p1.w) * 16.f)), v3);
        acc_h16h(a, __half2half2(__float2half_rn(__int_as_float(p2.y) * 16.f)), v4);
        acc_h16h(a, __half2half2(__float2half_rn(__int_as_float(p2.w) * 16.f)), v5);
        acc_h16h(a, __half2half2(__float2half_rn(__int_as_float(p3.y) * 16.f)), v6);
        acc_h16h(a, __half2half2(__float2half_rn(__int_as_float(p3.w) * 16.f)), v7);
    }
    for (; j < e; j++) {
        int2 c = g_csr[j];
        __half2 w2 = __half2half2(__float2half_rn(__int_as_float(c.y) * 16.f));
        acc_h16h(a, w2, ((const uint4*)(g_s16 + (size_t)c.x * DCOLS))[lane]);
    }

    // a = 16*h1 ; h1 fp16 = a/16 ; h1q fp8 = a
    const __half2 inv16 = __half2half2(__float2half(0.0625f));
    uint4 o;
    __half2 h0 = __hmul2(a[0], inv16), h1v = __hmul2(a[1], inv16);
    __half2 h2v = __hmul2(a[2], inv16), h3v = __hmul2(a[3], inv16);
    o.x = *(unsigned*)&h0; o.y = *(unsigned*)&h1v;
    o.z = *(unsigned*)&h2v; o.w = *(unsigned*)&h3v;
    ((uint4*)(g_h1 + (size_t)warp * DCOLS))[lane] = o;

    ushort4 q8;
    q8.x = h2_to_fp8x2(a[0]);
    q8.y = h2_to_fp8x2(a[1]);
    q8.z = h2_to_fp8x2(a[2]);
    q8.w = h2_to_fp8x2(a[3]);
    ((ushort4*)(g_h1q + (size_t)warp * DCOLS))[lane] = q8;
}

// hop2: gathers h1q (fp8 = h1*16), half2 accum (a = 16*h2);
// writes h2 fp16 + h2q fp8(=h2*256 = a*16)
__global__ __launch_bounds__(256) void spmm2_kernel(int M)
{
    const int warp = (blockIdx.x * blockDim.x + threadIdx.x) >> 5;
    if (warp >= M) return;
    const int lane = threadIdx.x & 31;
    const int s = g_row_start[warp];
    const int e = g_row_start[warp + 1];

    __half2 a[4];
#pragma unroll
    for (int q = 0; q < 4; q++) a[q] = __half2half2(__float2half(0.f));

    int j = s;
    if ((j & 1) && j < e) {
        int2 c = g_csr[j];
        acc_q8h(a, wh2(c.y), ((const uint2*)(g_h1q + (size_t)c.x * DCOLS))[lane]);
        j++;
    }
    for (; j + 7 < e; j += 8) {
        int4 p0 = *(const int4*)&g_csr[j];
        int4 p1 = *(const int4*)&g_csr[j + 2];
        int4 p2 = *(const int4*)&g_csr[j + 4];
        int4 p3 = *(const int4*)&g_csr[j + 6];
        uint2 v0 = ((const uint2*)(g_h1q + (size_t)p0.x * DCOLS))[lane];
        uint2 v1 = ((const uint2*)(g_h1q + (size_t)p0.z * DCOLS))[lane];
        uint2 v2 = ((const uint2*)(g_h1q + (size_t)p1.x * DCOLS))[lane];
        uint2 v3 = ((const uint2*)(g_h1q + (size_t)p1.z * DCOLS))[lane];
        uint2 v4 = ((const uint2*)(g_h1q + (size_t)p2.x * DCOLS))[lane];
        uint2 v5 = ((const uint2*)(g_h1q + (size_t)p2.z * DCOLS))[lane];
        uint2 v6 = ((const uint2*)(g_h1q + (size_t)p3.x * DCOLS))[lane];
        uint2 v7 = ((const uint2*)(g_h1q + (size_t)p3.z * DCOLS))[lane];
        acc_q8h(a, wh2(p0.y), v0);
        acc_q8h(a, wh2(p0.w), v1);
        acc_q8h(a, wh2(p1.y), v2);
        acc_q8h(a, wh2(p1.w), v3);
        acc_q8h(a, wh2(p2.y), v4);
        acc_q8h(a, wh2(p2.w), v5);
        acc_q8h(a, wh2(p3.y), v6);
        acc_q8h(a, wh2(p3.w), v7);
    }
    for (; j < e; j++) {
        int2 c = g_csr[j];
        acc_q8h(a, wh2(c.y), ((const uint2*)(g_h1q + (size_t)c.x * DCOLS))[lane]);
    }

    const __half2 inv16 = __half2half2(__float2half(0.0625f));
    const __half2 x16   = __half2half2(__float2half(16.f));
    uint4 o;
    __half2 h0 = __hmul2(a[0], inv16), h1v = __hmul2(a[1], inv16);
    __half2 h2v = __hmul2(a[2], inv16), h3v = __hmul2(a[3], inv16);
    o.x = *(unsigned*)&h0; o.y = *(unsigned*)&h1v;
    o.z = *(unsigned*)&h2v; o.w = *(unsigned*)&h3v;
    ((uint4*)(g_h2 + (size_t)warp * DCOLS))[lane] = o;

    ushort4 q8;
    q8.x = h2_to_fp8x2(__hmul2(a[0], x16));
    q8.y = h2_to_fp8x2(__hmul2(a[1], x16));
    q8.z = h2_to_fp8x2(__hmul2(a[2], x16));
    q8.w = h2_to_fp8x2(__hmul2(a[3], x16));
    ((ushort4*)(g_h2q + (size_t)warp * DCOLS))[lane] = q8;
}

// hop3 fused with combine: out = s16 + h1 + h2 + (A*h2q)/256 + bias
__global__ __launch_bounds__(256) void spmm3_combine_kernel(
    float* __restrict__ out, const float* __restrict__ bias, int M)
{
    const int warp = (blockIdx.x * blockDim.x + threadIdx.x) >> 5;
    if (warp >= M) return;
    const int lane = threadIdx.x & 31;
    const int s = g_row_start[warp];
    const int e = g_row_start[warp + 1];

    __half2 a[4];
#pragma unroll
    for (int q = 0; q < 4; q++) a[q] = __half2half2(__float2half(0.f));

    int j = s;
    if ((j & 1) && j < e) {
        int2 c = g_csr[j];
        acc_q8h(a, wh2(c.y), ((const uint2*)(g_h2q + (size_t)c.x * DCOLS))[lane]);
        j++;
    }
    for (; j + 7 < e; j += 8) {
        int4 p0 = *(const int4*)&g_csr[j];
        int4 p1 = *(const int4*)&g_csr[j + 2];
        int4 p2 = *(const int4*)&g_csr[j + 4];
        int4 p3 = *(const int4*)&g_csr[j + 6];
        uint2 v0 = ((const uint2*)(g_h2q + (size_t)p0.x * DCOLS))[lane];
        uint2 v1 = ((const uint2*)(g_h2q + (size_t)p0.z * DCOLS))[lane];
        uint2 v2 = ((const uint2*)(g_h2q + (size_t)p1.x * DCOLS))[lane];
        uint2 v3 = ((const uint2*)(g_h2q + (size_t)p1.z * DCOLS))[lane];
        uint2 v4 = ((const uint2*)(g_h2q + (size_t)p2.x * DCOLS))[lane];
        uint2 v5 = ((const uint2*)(g_h2q + (size_t)p2.z * DCOLS))[lane];
        uint2 v6 = ((const uint2*)(g_h2q + (size_t)p3.x * DCOLS))[lane];
        uint2 v7 = ((const uint2*)(g_h2q + (size_t)p3.z * DCOLS))[lane];
        acc_q8h(a, wh2(p0.y), v0);
        acc_q8h(a, wh2(p0.w), v1);
        acc_q8h(a, wh2(p1.y), v2);
        acc_q8h(a, wh2(p1.w), v3);
        acc_q8h(a, wh2(p2.y), v4);
        acc_q8h(a, wh2(p2.w), v5);
        acc_q8h(a, wh2(p3.y), v6);
        acc_q8h(a, wh2(p3.w), v7);
    }
    for (; j < e; j++) {
        int2 c = g_csr[j];
        acc_q8h(a, wh2(c.y), ((const uint2*)(g_h2q + (size_t)c.x * DCOLS))[lane]);
    }

    const size_t o = (size_t)warp * DCOLS + lane * 8;
    float4 b0 = *(const float4*)(bias + lane * 8);
    float4 b1 = *(const float4*)(bias + lane * 8 + 4);
    uint4 us = ((const uint4*)(g_s16 + (size_t)warp * DCOLS))[lane];
    uint4 u1 = ((const uint4*)(g_h1 + (size_t)warp * DCOLS))[lane];
    uint4 u2 = ((const uint4*)(g_h2 + (size_t)warp * DCOLS))[lane];
    const __half2* hs = (const __half2*)&us;
    const __half2* h1 = (const __half2*)&u1;
    const __half2* h2 = (const __half2*)&u2;

    float r[8];
#pragma unroll
    for (int q = 0; q < 4; q++) {
        float2 fs = __half22float2(hs[q]);
        float2 f1 = __half22float2(h1[q]);
        float2 f2 = __half22float2(h2[q]);
        float2 f3 = __half22float2(a[q]);          // = 256 * h3
        r[2 * q + 0] = fs.x + f1.x + f2.x + f3.x * (1.f / 256.f);
        r[2 * q + 1] = fs.y + f1.y + f2.y + f3.y * (1.f / 256.f);
    }
    float4 o0 = make_float4(r[0] + b0.x, r[1] + b0.y, r[2] + b0.z, r[3] + b0.w);
    float4 o1 = make_float4(r[4] + b1.x, r[5] + b1.y, r[6] + b1.z, r[7] + b1.w);
    *(float4*)(out + o) = o0;
    *(float4*)(out + o + 4) = o1;
}

// ======================= launch ============================================
extern "C" void kernel_launch(void* const* d_in, const int* in_sizes, int n_in,
                              void* d_out, int out_size)
{
    const float* x    = (const float*)d_in[0];
    const float* w    = (const float*)d_in[1];
    const float* bias = (const float*)d_in[2];
    const float* ew   = (const float*)d_in[3];
    const int*   er   = (const int*)d_in[4];
    const int*   ec   = (const int*)d_in[5];
    float* out = (float*)d_out;

    const int M = in_sizes[0] / DCOLS;
    const int E = in_sizes[3];
    const int NB = (M + 1023) / 1024;

    cudaStream_t s2;
    cudaEvent_t eFork, eJoin;
    cudaStreamCreateWithFlags(&s2, cudaStreamNonBlocking);
    cudaEventCreateWithFlags(&eFork, cudaEventDisableTiming);
    cudaEventCreateWithFlags(&eJoin, cudaEventDisableTiming);

    cudaEventRecord(eFork, 0);
    cudaStreamWaitEvent(s2, eFork, 0);

    // main stream: fp16 tensor-core GEMM
    dim3 ggrid(DCOLS / GBN, (M + GBM - 1) / GBM);
    gemm_f16_kernel<<<ggrid, 256>>>(x, w, M);

    // side stream: CSR build
    zero_counts_kernel<<<(M + 255) / 256, 256, 0, s2>>>(M);
    count_kernel<<<1024, 256, 0, s2>>>(er, E);
    local_scan_kernel<<<NB, 1024, 0, s2>>>(M);
    scan_sums_kernel<<<1, 128, 0, s2>>>(NB);
    add_off_kernel<<<NB, 1024, 0, s2>>>(M, E);
    scatter_kernel<<<1024, 256, 0, s2>>>(er, ec, ew, E);

    cudaEventRecord(eJoin, s2);
    cudaStreamWaitEvent(0, eJoin, 0);

    // hops
    const int sblocks = (int)(((size_t)M * 32 + 255) / 256);
    spmm1_kernel<<<sblocks, 256>>>(M);
    spmm2_kernel<<<sblocks, 256>>>(M);
    spmm3_combine_kernel<<<sblocks, 256>>>(out, bias, M);

    cudaEventDestroy(eFork);
    cudaEventDestroy(eJoin);
    cudaStreamDestroy(s2);
}